// round 2
// baseline (speedup 1.0000x reference)
#include <cuda_runtime.h>
#include <math.h>

#define Pp 16384
#define Dd 128
#define Bb 4
#define Nn 6
#define Mm 65536   // B*P rows

// ---- scratch (static device globals; no allocation allowed) ----
__device__ float refT_g[(size_t)Bb * Nn * Pp * Dd];  // (bn, p, d)  201 MB
__device__ float qT_g[(size_t)Bb * Pp * Dd];         // (bp, d)      32 MB
__device__ float ztLN_g[(size_t)Bb * Pp * Dd];       // (bp, d)      32 MB
__device__ float hbuf_g[(size_t)Mm * 256];           // (bp, 2d)     64 MB

// ---------------------------------------------------------------
// helpers
// ---------------------------------------------------------------
__device__ __forceinline__ float warpsum(float v) {
#pragma unroll
    for (int s = 16; s; s >>= 1) v += __shfl_xor_sync(0xffffffffu, v, s);
    return v;
}

__device__ __forceinline__ float gelu_exact(float x) {
    return 0.5f * x * (1.0f + erff(x * 0.70710678118654752440f));
}

// ---------------------------------------------------------------
// Transpose (mat, D=128, P=16384) -> (mat, P, D)
// ---------------------------------------------------------------
__device__ __forceinline__ void transpose_128xP(const float* __restrict__ in,
                                                float* __restrict__ out) {
    __shared__ float tile[32][33];
    int mat = blockIdx.z;
    const float* src = in + (size_t)mat * Dd * Pp;
    float* dst = out + (size_t)mat * Dd * Pp;
    int p0 = blockIdx.x * 32, d0 = blockIdx.y * 32;
#pragma unroll
    for (int i = threadIdx.y; i < 32; i += 8)
        tile[i][threadIdx.x] = src[(size_t)(d0 + i) * Pp + p0 + threadIdx.x];
    __syncthreads();
#pragma unroll
    for (int i = threadIdx.y; i < 32; i += 8)
        dst[(size_t)(p0 + i) * Dd + d0 + threadIdx.x] = tile[threadIdx.x][i];
}

__global__ void transpose_ref_kernel(const float* __restrict__ in) {
    transpose_128xP(in, refT_g);
}
__global__ void transpose_q_kernel(const float* __restrict__ in) {
    transpose_128xP(in, qT_g);
}

// ---------------------------------------------------------------
// Attention: bilinear gather + cosine dot + softmax over N=6 +
//            weighted sum + residual + LayerNorm1.
// One warp per pixel; each lane owns 4 channels (d = k*32 + lane).
// ---------------------------------------------------------------
__global__ void __launch_bounds__(256) attn_kernel(const float* __restrict__ homo,
                                                   const float* __restrict__ ln1w,
                                                   const float* __restrict__ ln1b) {
    int lane = threadIdx.x & 31;
    int warp = threadIdx.x >> 5;
    int gp = blockIdx.x * 8 + warp;   // global pixel row 0..65535
    int b = gp >> 14;
    int p = gp & (Pp - 1);

    const float* qrow = qT_g + (size_t)gp * Dd;
    float q[4];
#pragma unroll
    for (int k = 0; k < 4; k++) q[k] = qrow[k * 32 + lane];
    float qn2 = warpsum(q[0] * q[0] + q[1] * q[1] + q[2] * q[2] + q[3] * q[3]);
    float qden = fmaxf(sqrtf(qn2), 1e-12f);

    float vals[6][4];
    float dots[6];

#pragma unroll
    for (int n = 0; n < 6; n++) {
        int bn = b * Nn + n;
        float u = homo[(size_t)(bn * 2 + 0) * Pp + p] * 128.0f;
        float v = homo[(size_t)(bn * 2 + 1) * Pp + p] * 128.0f;
        float x0f = floorf(u), y0f = floorf(v);
        float wx = u - x0f, wy = v - y0f;
        int ix0 = min(max(__float2int_rd(u), 0), 127);
        int ix1 = min(max(__float2int_rd(u) + 1, 0), 127);
        int iy0 = min(max(__float2int_rd(v), 0), 127);
        int iy1 = min(max(__float2int_rd(v) + 1, 0), 127);
        bool valid = (u >= 0.0f) && (u <= 127.0f) && (v >= 0.0f) && (v <= 127.0f);

        const float* base = refT_g + (size_t)bn * Pp * Dd;
        const float* p00 = base + (size_t)(iy0 * 128 + ix0) * Dd;
        const float* p10 = base + (size_t)(iy0 * 128 + ix1) * Dd;
        const float* p01 = base + (size_t)(iy1 * 128 + ix0) * Dd;
        const float* p11 = base + (size_t)(iy1 * 128 + ix1) * Dd;

        float w00 = (1.0f - wx) * (1.0f - wy);
        float w10 = wx * (1.0f - wy);
        float w01 = (1.0f - wx) * wy;
        float w11 = wx * wy;

        float s = 0.0f, v2 = 0.0f;
#pragma unroll
        for (int k = 0; k < 4; k++) {
            int d = k * 32 + lane;
            float val = w00 * p00[d] + w10 * p10[d] + w01 * p01[d] + w11 * p11[d];
            vals[n][k] = val;
            v2 += val * val;
            s += q[k] * val;
        }
        v2 = warpsum(v2);
        s = warpsum(s);
        float vden = fmaxf(sqrtf(v2), 1e-12f);
        dots[n] = valid ? (s / (qden * vden)) : 0.0f;
    }

    // softmax over n
    float m = dots[0];
#pragma unroll
    for (int n = 1; n < 6; n++) m = fmaxf(m, dots[n]);
    float e[6], esum = 0.0f;
#pragma unroll
    for (int n = 0; n < 6; n++) { e[n] = expf(dots[n] - m); esum += e[n]; }
    float inv = 1.0f / esum;

    float zt[4];
#pragma unroll
    for (int k = 0; k < 4; k++) {
        float z = 0.0f;
#pragma unroll
        for (int n = 0; n < 6; n++) z += e[n] * vals[n][k];
        zt[k] = q[k] + z * inv;
    }

    // LayerNorm1
    float mean = warpsum(zt[0] + zt[1] + zt[2] + zt[3]) * (1.0f / 128.0f);
    float dv = 0.0f;
#pragma unroll
    for (int k = 0; k < 4; k++) { float dd = zt[k] - mean; dv += dd * dd; }
    float var = warpsum(dv) * (1.0f / 128.0f);
    float rstd = rsqrtf(var + 1e-5f);
#pragma unroll
    for (int k = 0; k < 4; k++) {
        int d = k * 32 + lane;
        ztLN_g[(size_t)gp * Dd + d] = (zt[k] - mean) * rstd * ln1w[d] + ln1b[d];
    }
}

// ---------------------------------------------------------------
// GEMM1: H = gelu(ztLN @ W1 + b1)   (65536x128)@(128x256)
// 64x64 tile, 256 threads, 4x4 micro-tile, BK=64
// ---------------------------------------------------------------
__global__ void __launch_bounds__(256) gemm1_kernel(const float* __restrict__ W1,
                                                    const float* __restrict__ b1) {
    __shared__ float As[64][64];
    __shared__ float Bs[64][64];
    int tid = threadIdx.x;
    int rowBase = blockIdx.x * 64;
    int colBase = blockIdx.y * 64;
    int tx = tid & 15, ty = tid >> 4;
    float acc[4][4] = {};

    for (int k0 = 0; k0 < 128; k0 += 64) {
#pragma unroll
        for (int t = 0; t < 4; t++) {
            int idx = tid + t * 256;          // 0..1023
            int r = idx >> 4;
            int kc = (idx & 15) << 2;
            *(float4*)&As[r][kc] =
                *(const float4*)(ztLN_g + (size_t)(rowBase + r) * 128 + k0 + kc);
        }
#pragma unroll
        for (int t = 0; t < 4; t++) {
            int idx = tid + t * 256;
            int k = idx >> 4;
            int c = (idx & 15) << 2;
            *(float4*)&Bs[k][c] =
                *(const float4*)(W1 + (size_t)(k0 + k) * 256 + colBase + c);
        }
        __syncthreads();
#pragma unroll 16
        for (int k = 0; k < 64; k++) {
            float4 bv = *(float4*)&Bs[k][tx * 4];
            float a0 = As[ty * 4 + 0][k];
            float a1 = As[ty * 4 + 1][k];
            float a2 = As[ty * 4 + 2][k];
            float a3 = As[ty * 4 + 3][k];
            acc[0][0] += a0 * bv.x; acc[0][1] += a0 * bv.y; acc[0][2] += a0 * bv.z; acc[0][3] += a0 * bv.w;
            acc[1][0] += a1 * bv.x; acc[1][1] += a1 * bv.y; acc[1][2] += a1 * bv.z; acc[1][3] += a1 * bv.w;
            acc[2][0] += a2 * bv.x; acc[2][1] += a2 * bv.y; acc[2][2] += a2 * bv.z; acc[2][3] += a2 * bv.w;
            acc[3][0] += a3 * bv.x; acc[3][1] += a3 * bv.y; acc[3][2] += a3 * bv.z; acc[3][3] += a3 * bv.w;
        }
        __syncthreads();
    }

    int c = colBase + tx * 4;
    float4 bb = *(const float4*)(b1 + c);
#pragma unroll
    for (int i = 0; i < 4; i++) {
        float4 o;
        o.x = gelu_exact(acc[i][0] + bb.x);
        o.y = gelu_exact(acc[i][1] + bb.y);
        o.z = gelu_exact(acc[i][2] + bb.z);
        o.w = gelu_exact(acc[i][3] + bb.w);
        *(float4*)(hbuf_g + (size_t)(rowBase + ty * 4 + i) * 256 + c) = o;
    }
}

// ---------------------------------------------------------------
// GEMM2: zt2 = ztLN + H @ W2 + b2; LN2; transposed write to out.
// (65536x256)@(256x128). BM=64, BN=128 (full rows), BK=32.
// 256 threads, 4x8 micro-tile. LN2 via 16-lane shuffle reduction.
// ---------------------------------------------------------------
__global__ void __launch_bounds__(256) gemm2_kernel(const float* __restrict__ W2,
                                                    const float* __restrict__ b2,
                                                    const float* __restrict__ ln2w,
                                                    const float* __restrict__ ln2b,
                                                    float* __restrict__ out) {
    __shared__ float As[64][32];
    __shared__ float Bs[32][128];
    int tid = threadIdx.x;
    int rowBase = blockIdx.x * 64;
    int tx = tid & 15, ty = tid >> 4;
    float acc[4][8] = {};

    for (int k0 = 0; k0 < 256; k0 += 32) {
#pragma unroll
        for (int t = 0; t < 2; t++) {
            int idx = tid + t * 256;          // 0..511
            int r = idx >> 3;
            int kc = (idx & 7) << 2;
            *(float4*)&As[r][kc] =
                *(const float4*)(hbuf_g + (size_t)(rowBase + r) * 256 + k0 + kc);
        }
#pragma unroll
        for (int t = 0; t < 4; t++) {
            int idx = tid + t * 256;          // 0..1023
            int k = idx >> 5;
            int c = (idx & 31) << 2;
            *(float4*)&Bs[k][c] =
                *(const float4*)(W2 + (size_t)(k0 + k) * 128 + c);
        }
        __syncthreads();
#pragma unroll 8
        for (int k = 0; k < 32; k++) {
            float4 b0 = *(float4*)&Bs[k][tx * 8];
            float4 b1v = *(float4*)&Bs[k][tx * 8 + 4];
#pragma unroll
            for (int i = 0; i < 4; i++) {
                float a = As[ty * 4 + i][k];
                acc[i][0] += a * b0.x;  acc[i][1] += a * b0.y;
                acc[i][2] += a * b0.z;  acc[i][3] += a * b0.w;
                acc[i][4] += a * b1v.x; acc[i][5] += a * b1v.y;
                acc[i][6] += a * b1v.z; acc[i][7] += a * b1v.w;
            }
        }
        __syncthreads();
    }

    // epilogue: + ztLN + b2, LN2, transposed store
    int b = rowBase >> 14;
    int prow = (rowBase & (Pp - 1)) + ty * 4;
    float4 bb0 = *(const float4*)(b2 + tx * 8);
    float4 bb1 = *(const float4*)(b2 + tx * 8 + 4);
    float mean[4], rstd[4];
#pragma unroll
    for (int i = 0; i < 4; i++) {
        const float* zr = ztLN_g + (size_t)(rowBase + ty * 4 + i) * 128 + tx * 8;
        float4 z0 = *(const float4*)zr;
        float4 z1 = *(const float4*)(zr + 4);
        acc[i][0] += z0.x + bb0.x; acc[i][1] += z0.y + bb0.y;
        acc[i][2] += z0.z + bb0.z; acc[i][3] += z0.w + bb0.w;
        acc[i][4] += z1.x + bb1.x; acc[i][5] += z1.y + bb1.y;
        acc[i][6] += z1.z + bb1.z; acc[i][7] += z1.w + bb1.w;
        float s = 0.0f, qq = 0.0f;
#pragma unroll
        for (int j = 0; j < 8; j++) { s += acc[i][j]; qq += acc[i][j] * acc[i][j]; }
#pragma unroll
        for (int sh = 1; sh < 16; sh <<= 1) {
            s += __shfl_xor_sync(0xffffffffu, s, sh);
            qq += __shfl_xor_sync(0xffffffffu, qq, sh);
        }
        mean[i] = s * (1.0f / 128.0f);
        float var = qq * (1.0f / 128.0f) - mean[i] * mean[i];
        rstd[i] = rsqrtf(var + 1e-5f);
    }
#pragma unroll
    for (int j = 0; j < 8; j++) {
        int c = tx * 8 + j;
        float lw = ln2w[c], lb = ln2b[c];
        float4 o;
        o.x = (acc[0][j] - mean[0]) * rstd[0] * lw + lb;
        o.y = (acc[1][j] - mean[1]) * rstd[1] * lw + lb;
        o.z = (acc[2][j] - mean[2]) * rstd[2] * lw + lb;
        o.w = (acc[3][j] - mean[3]) * rstd[3] * lw + lb;
        *(float4*)(out + ((size_t)(b * 128 + c)) * Pp + prow) = o;
    }
}

// ---------------------------------------------------------------
extern "C" void kernel_launch(void* const* d_in, const int* in_sizes, int n_in,
                              void* d_out, int out_size) {
    const float* query = (const float*)d_in[0];
    const float* ref   = (const float*)d_in[1];
    const float* homo  = (const float*)d_in[2];
    const float* ln1w  = (const float*)d_in[3];
    const float* ln1b  = (const float*)d_in[4];
    const float* ln2w  = (const float*)d_in[5];
    const float* ln2b  = (const float*)d_in[6];
    const float* w1    = (const float*)d_in[7];
    const float* b1    = (const float*)d_in[8];
    const float* w2    = (const float*)d_in[9];
    const float* b2    = (const float*)d_in[10];
    float* out = (float*)d_out;

    dim3 tb(32, 8);
    transpose_ref_kernel<<<dim3(Pp / 32, Dd / 32, Bb * Nn), tb>>>(ref);
    transpose_q_kernel<<<dim3(Pp / 32, Dd / 32, Bb), tb>>>(query);
    attn_kernel<<<Mm / 8, 256>>>(homo, ln1w, ln1b);
    gemm1_kernel<<<dim3(Mm / 64, 256 / 64), 256>>>(w1, b1);
    gemm2_kernel<<<Mm / 64, 256>>>(w2, b2, ln2w, ln2b, out);
}

// round 4
// speedup vs baseline: 1.1421x; 1.1421x over previous
#include <cuda_runtime.h>
#include <cuda_fp16.h>
#include <math.h>

#define Pp 16384
#define Dd 128
#define Bb 4
#define Nn 6
#define Mm 65536   // B*P rows

// ---- scratch (static device globals; no allocation allowed) ----
__device__ __half  refTh_g[(size_t)Bb * Nn * Pp * Dd]; // (bn, p, d) fp16, 201MB
__device__ float   qT_g[(size_t)Bb * Pp * Dd];         // (bp, d)  32 MB
__device__ float   ztLN_g[(size_t)Bb * Pp * Dd];       // (bp, d)  32 MB
__device__ float   hbuf_g[(size_t)Mm * 256];           // (bp, 2d) 64 MB

// ---------------------------------------------------------------
// helpers
// ---------------------------------------------------------------
__device__ __forceinline__ float warpsum(float v) {
#pragma unroll
    for (int s = 16; s; s >>= 1) v += __shfl_xor_sync(0xffffffffu, v, s);
    return v;
}
__device__ __forceinline__ float gelu_exact(float x) {
    return 0.5f * x * (1.0f + erff(x * 0.70710678118654752440f));
}
__device__ __forceinline__ void ffma2(unsigned long long& d,
                                      unsigned long long a,
                                      unsigned long long b) {
    asm("fma.rn.f32x2 %0, %1, %2, %0;" : "+l"(d) : "l"(a), "l"(b));
}
__device__ __forceinline__ float2 unpack2(unsigned long long v) {
    float2 f;
    asm("mov.b64 {%0, %1}, %2;" : "=f"(f.x), "=f"(f.y) : "l"(v));
    return f;
}
__device__ __forceinline__ float4 ldg_half4(const __half* p) {
    uint2 u = *(const uint2*)p;
    __half2 h0 = *reinterpret_cast<__half2*>(&u.x);
    __half2 h1 = *reinterpret_cast<__half2*>(&u.y);
    float2 f0 = __half22float2(h0), f1 = __half22float2(h1);
    return make_float4(f0.x, f0.y, f1.x, f1.y);
}

// ---------------------------------------------------------------
// Transpose ref (mat, D=128, P) -> fp16 (mat, P, D)
// Block: 256 threads, handles 32 p-rows x all 128 d.
// ---------------------------------------------------------------
__global__ void __launch_bounds__(256) transpose_ref_h_kernel(const float* __restrict__ in) {
    __shared__ float tile[32][129];
    int mat = blockIdx.z;
    int p0 = blockIdx.x * 32;
    const float* src = in + (size_t)mat * Dd * Pp;
    __half* dst = refTh_g + (size_t)mat * Pp * Dd;

    int lane = threadIdx.x & 31;
    int ty = threadIdx.x >> 5;           // 0..7
#pragma unroll
    for (int it = 0; it < 16; it++) {
        int d = it * 8 + ty;
        tile[lane][d] = src[(size_t)d * Pp + p0 + lane];
    }
    __syncthreads();
    int pi = threadIdx.x & 63;           // half2 index 0..63
    int ppb = threadIdx.x >> 6;          // 0..3
#pragma unroll
    for (int it = 0; it < 8; it++) {
        int pp = it * 4 + ppb;
        float2 f = make_float2(tile[pp][2 * pi], tile[pp][2 * pi + 1]);
        *(__half2*)(dst + (size_t)(p0 + pp) * Dd + 2 * pi) = __float22half2_rn(f);
    }
}

// ---------------------------------------------------------------
// Transpose q (b, D=128, P) -> fp32 (b, P, D)
// ---------------------------------------------------------------
__global__ void transpose_q_kernel(const float* __restrict__ in) {
    __shared__ float tile[32][33];
    int mat = blockIdx.z;
    const float* src = in + (size_t)mat * Dd * Pp;
    float* dst = qT_g + (size_t)mat * Dd * Pp;
    int p0 = blockIdx.x * 32, d0 = blockIdx.y * 32;
#pragma unroll
    for (int i = threadIdx.y; i < 32; i += 8)
        tile[i][threadIdx.x] = src[(size_t)(d0 + i) * Pp + p0 + threadIdx.x];
    __syncthreads();
#pragma unroll
    for (int i = threadIdx.y; i < 32; i += 8)
        dst[(size_t)(p0 + i) * Dd + d0 + threadIdx.x] = tile[threadIdx.x][i];
}

// ---------------------------------------------------------------
// Attention: bilinear gather(fp16) + cosine dot + softmax(N=6) +
//            weighted sum + residual + LayerNorm1.
// One warp per pixel; lane owns channels lane*4 .. lane*4+3.
// ---------------------------------------------------------------
__global__ void __launch_bounds__(256) attn_kernel(const float* __restrict__ homo,
                                                   const float* __restrict__ ln1w,
                                                   const float* __restrict__ ln1b) {
    int lane = threadIdx.x & 31;
    int warp = threadIdx.x >> 5;
    int gp = blockIdx.x * 8 + warp;   // pixel row 0..65535
    int b = gp >> 14;
    int p = gp & (Pp - 1);

    float4 qv = *(const float4*)(qT_g + (size_t)gp * Dd + lane * 4);
    float qn2 = warpsum(qv.x * qv.x + qv.y * qv.y + qv.z * qv.z + qv.w * qv.w);
    float qden = fmaxf(sqrtf(qn2), 1e-12f);

    float4 vals[6];
    float dots[6];

#pragma unroll
    for (int n = 0; n < 6; n++) {
        int bn = b * Nn + n;
        float u = homo[(size_t)(bn * 2 + 0) * Pp + p] * 128.0f;
        float v = homo[(size_t)(bn * 2 + 1) * Pp + p] * 128.0f;
        float wx = u - floorf(u), wy = v - floorf(v);
        int ix0 = min(max(__float2int_rd(u), 0), 127);
        int ix1 = min(max(__float2int_rd(u) + 1, 0), 127);
        int iy0 = min(max(__float2int_rd(v), 0), 127);
        int iy1 = min(max(__float2int_rd(v) + 1, 0), 127);
        bool valid = (u >= 0.0f) && (u <= 127.0f) && (v >= 0.0f) && (v <= 127.0f);

        const __half* base = refTh_g + (size_t)bn * Pp * Dd + lane * 4;
        float4 v00 = ldg_half4(base + (size_t)(iy0 * 128 + ix0) * Dd);
        float4 v10 = ldg_half4(base + (size_t)(iy0 * 128 + ix1) * Dd);
        float4 v01 = ldg_half4(base + (size_t)(iy1 * 128 + ix0) * Dd);
        float4 v11 = ldg_half4(base + (size_t)(iy1 * 128 + ix1) * Dd);

        float w00 = (1.0f - wx) * (1.0f - wy);
        float w10 = wx * (1.0f - wy);
        float w01 = (1.0f - wx) * wy;
        float w11 = wx * wy;

        float4 val;
        val.x = w00 * v00.x + w10 * v10.x + w01 * v01.x + w11 * v11.x;
        val.y = w00 * v00.y + w10 * v10.y + w01 * v01.y + w11 * v11.y;
        val.z = w00 * v00.z + w10 * v10.z + w01 * v01.z + w11 * v11.z;
        val.w = w00 * v00.w + w10 * v10.w + w01 * v01.w + w11 * v11.w;
        vals[n] = val;

        float v2 = val.x * val.x + val.y * val.y + val.z * val.z + val.w * val.w;
        float s  = qv.x * val.x + qv.y * val.y + qv.z * val.z + qv.w * val.w;
        v2 = warpsum(v2);
        s = warpsum(s);
        float vden = fmaxf(sqrtf(v2), 1e-12f);
        dots[n] = valid ? (s / (qden * vden)) : 0.0f;
    }

    float m = dots[0];
#pragma unroll
    for (int n = 1; n < 6; n++) m = fmaxf(m, dots[n]);
    float e[6], esum = 0.0f;
#pragma unroll
    for (int n = 0; n < 6; n++) { e[n] = expf(dots[n] - m); esum += e[n]; }
    float inv = 1.0f / esum;

    float zt[4];
    zt[0] = qv.x; zt[1] = qv.y; zt[2] = qv.z; zt[3] = qv.w;
#pragma unroll
    for (int k = 0; k < 4; k++) {
        float z = 0.0f;
        z += e[0] * ((const float*)&vals[0])[k];
        z += e[1] * ((const float*)&vals[1])[k];
        z += e[2] * ((const float*)&vals[2])[k];
        z += e[3] * ((const float*)&vals[3])[k];
        z += e[4] * ((const float*)&vals[4])[k];
        z += e[5] * ((const float*)&vals[5])[k];
        zt[k] += z * inv;
    }

    float mean = warpsum(zt[0] + zt[1] + zt[2] + zt[3]) * (1.0f / 128.0f);
    float dv = 0.0f;
#pragma unroll
    for (int k = 0; k < 4; k++) { float dd = zt[k] - mean; dv += dd * dd; }
    float rstd = rsqrtf(warpsum(dv) * (1.0f / 128.0f) + 1e-5f);

    float4 lw = *(const float4*)(ln1w + lane * 4);
    float4 lb = *(const float4*)(ln1b + lane * 4);
    float4 o;
    o.x = (zt[0] - mean) * rstd * lw.x + lb.x;
    o.y = (zt[1] - mean) * rstd * lw.y + lb.y;
    o.z = (zt[2] - mean) * rstd * lw.z + lb.z;
    o.w = (zt[3] - mean) * rstd * lw.w + lb.w;
    *(float4*)(ztLN_g + (size_t)gp * Dd + lane * 4) = o;
}

// ---------------------------------------------------------------
// GEMM1: H = gelu(ztLN @ W1 + b1)   (65536x128)@(128x256)
// BM=128, BN=128, BK=16, 256 threads, 8x8 micro-tile, FFMA2.
// ---------------------------------------------------------------
__global__ void __launch_bounds__(256, 2) gemm1_kernel(const float* __restrict__ W1,
                                                       const float* __restrict__ b1) {
    __shared__ float2 As2[16][128];   // duplicated A: (a,a)
    __shared__ float  Bs[16][128];
    int tid = threadIdx.x;
    int rowBase = blockIdx.x * 128;
    int colBase = blockIdx.y * 128;
    int tx = tid & 15, ty = tid >> 4;
    unsigned long long acc[8][4] = {};

    for (int k0 = 0; k0 < 128; k0 += 16) {
#pragma unroll
        for (int t = 0; t < 2; t++) {
            int idx = tid + t * 256;          // 0..511
            int r = idx >> 2;
            int kc = (idx & 3) << 2;
            float4 a = *(const float4*)(ztLN_g + (size_t)(rowBase + r) * 128 + k0 + kc);
            As2[kc + 0][r] = make_float2(a.x, a.x);
            As2[kc + 1][r] = make_float2(a.y, a.y);
            As2[kc + 2][r] = make_float2(a.z, a.z);
            As2[kc + 3][r] = make_float2(a.w, a.w);
        }
#pragma unroll
        for (int t = 0; t < 2; t++) {
            int idx = tid + t * 256;
            int k = idx >> 5;
            int c = (idx & 31) << 2;
            *(float4*)&Bs[k][c] =
                *(const float4*)(W1 + (size_t)(k0 + k) * 256 + colBase + c);
        }
        __syncthreads();
#pragma unroll 4
        for (int k = 0; k < 16; k++) {
            ulonglong2 a01 = *(const ulonglong2*)&As2[k][ty * 8 + 0];
            ulonglong2 a23 = *(const ulonglong2*)&As2[k][ty * 8 + 2];
            ulonglong2 a45 = *(const ulonglong2*)&As2[k][ty * 8 + 4];
            ulonglong2 a67 = *(const ulonglong2*)&As2[k][ty * 8 + 6];
            ulonglong2 b03 = *(const ulonglong2*)&Bs[k][tx * 8];
            ulonglong2 b47 = *(const ulonglong2*)&Bs[k][tx * 8 + 4];
            unsigned long long A[8] = {a01.x, a01.y, a23.x, a23.y,
                                       a45.x, a45.y, a67.x, a67.y};
            unsigned long long Bv[4] = {b03.x, b03.y, b47.x, b47.y};
#pragma unroll
            for (int i = 0; i < 8; i++) {
#pragma unroll
                for (int jp = 0; jp < 4; jp++) ffma2(acc[i][jp], A[i], Bv[jp]);
            }
        }
        __syncthreads();
    }

    int c = colBase + tx * 8;
    float4 bb0 = *(const float4*)(b1 + c);
    float4 bb1 = *(const float4*)(b1 + c + 4);
#pragma unroll
    for (int i = 0; i < 8; i++) {
        float2 f0 = unpack2(acc[i][0]);
        float2 f1 = unpack2(acc[i][1]);
        float2 f2 = unpack2(acc[i][2]);
        float2 f3 = unpack2(acc[i][3]);
        float4 o0, o1;
        o0.x = gelu_exact(f0.x + bb0.x); o0.y = gelu_exact(f0.y + bb0.y);
        o0.z = gelu_exact(f1.x + bb0.z); o0.w = gelu_exact(f1.y + bb0.w);
        o1.x = gelu_exact(f2.x + bb1.x); o1.y = gelu_exact(f2.y + bb1.y);
        o1.z = gelu_exact(f3.x + bb1.z); o1.w = gelu_exact(f3.y + bb1.w);
        float* dst = hbuf_g + (size_t)(rowBase + ty * 8 + i) * 256 + c;
        *(float4*)dst = o0;
        *(float4*)(dst + 4) = o1;
    }
}

// ---------------------------------------------------------------
// GEMM2: zt2 = ztLN + H @ W2 + b2; LN2; transposed write to out.
// (65536x256)@(256x128). BM=128, BN=128(full), BK=16, 8x8 micro, FFMA2.
// ---------------------------------------------------------------
__global__ void __launch_bounds__(256, 2) gemm2_kernel(const float* __restrict__ W2,
                                                       const float* __restrict__ b2,
                                                       const float* __restrict__ ln2w,
                                                       const float* __restrict__ ln2b,
                                                       float* __restrict__ out) {
    __shared__ float2 As2[16][128];
    __shared__ float  Bs[16][128];
    int tid = threadIdx.x;
    int rowBase = blockIdx.x * 128;
    int tx = tid & 15, ty = tid >> 4;
    unsigned long long acc[8][4] = {};

    for (int k0 = 0; k0 < 256; k0 += 16) {
#pragma unroll
        for (int t = 0; t < 2; t++) {
            int idx = tid + t * 256;
            int r = idx >> 2;
            int kc = (idx & 3) << 2;
            float4 a = *(const float4*)(hbuf_g + (size_t)(rowBase + r) * 256 + k0 + kc);
            As2[kc + 0][r] = make_float2(a.x, a.x);
            As2[kc + 1][r] = make_float2(a.y, a.y);
            As2[kc + 2][r] = make_float2(a.z, a.z);
            As2[kc + 3][r] = make_float2(a.w, a.w);
        }
#pragma unroll
        for (int t = 0; t < 2; t++) {
            int idx = tid + t * 256;
            int k = idx >> 5;
            int c = (idx & 31) << 2;
            *(float4*)&Bs[k][c] =
                *(const float4*)(W2 + (size_t)(k0 + k) * 128 + c);
        }
        __syncthreads();
#pragma unroll 4
        for (int k = 0; k < 16; k++) {
            ulonglong2 a01 = *(const ulonglong2*)&As2[k][ty * 8 + 0];
            ulonglong2 a23 = *(const ulonglong2*)&As2[k][ty * 8 + 2];
            ulonglong2 a45 = *(const ulonglong2*)&As2[k][ty * 8 + 4];
            ulonglong2 a67 = *(const ulonglong2*)&As2[k][ty * 8 + 6];
            ulonglong2 b03 = *(const ulonglong2*)&Bs[k][tx * 8];
            ulonglong2 b47 = *(const ulonglong2*)&Bs[k][tx * 8 + 4];
            unsigned long long A[8] = {a01.x, a01.y, a23.x, a23.y,
                                       a45.x, a45.y, a67.x, a67.y};
            unsigned long long Bv[4] = {b03.x, b03.y, b47.x, b47.y};
#pragma unroll
            for (int i = 0; i < 8; i++) {
#pragma unroll
                for (int jp = 0; jp < 4; jp++) ffma2(acc[i][jp], A[i], Bv[jp]);
            }
        }
        __syncthreads();
    }

    // epilogue: + ztLN + b2, LN2 (row of 128 across 16 tx lanes), transposed store
    int b = rowBase >> 14;
    int prowBase = (rowBase & (Pp - 1)) + ty * 8;
    float4 bb0 = *(const float4*)(b2 + tx * 8);
    float4 bb1 = *(const float4*)(b2 + tx * 8 + 4);

    float accf[8][8];
    float mean[8], rstd[8];
#pragma unroll
    for (int i = 0; i < 8; i++) {
        const float* zr = ztLN_g + (size_t)(rowBase + ty * 8 + i) * 128 + tx * 8;
        float4 z0 = *(const float4*)zr;
        float4 z1 = *(const float4*)(zr + 4);
        float2 f0 = unpack2(acc[i][0]);
        float2 f1 = unpack2(acc[i][1]);
        float2 f2 = unpack2(acc[i][2]);
        float2 f3 = unpack2(acc[i][3]);
        accf[i][0] = f0.x + z0.x + bb0.x; accf[i][1] = f0.y + z0.y + bb0.y;
        accf[i][2] = f1.x + z0.z + bb0.z; accf[i][3] = f1.y + z0.w + bb0.w;
        accf[i][4] = f2.x + z1.x + bb1.x; accf[i][5] = f2.y + z1.y + bb1.y;
        accf[i][6] = f3.x + z1.z + bb1.z; accf[i][7] = f3.y + z1.w + bb1.w;
        float s = 0.0f, qq = 0.0f;
#pragma unroll
        for (int j = 0; j < 8; j++) { s += accf[i][j]; qq += accf[i][j] * accf[i][j]; }
#pragma unroll
        for (int sh = 1; sh < 16; sh <<= 1) {
            s += __shfl_xor_sync(0xffffffffu, s, sh);
            qq += __shfl_xor_sync(0xffffffffu, qq, sh);
        }
        mean[i] = s * (1.0f / 128.0f);
        float var = qq * (1.0f / 128.0f) - mean[i] * mean[i];
        rstd[i] = rsqrtf(var + 1e-5f);
    }
#pragma unroll
    for (int j = 0; j < 8; j++) {
        int c = tx * 8 + j;
        float lw = ln2w[c], lb = ln2b[c];
        float4 o0, o1;
        o0.x = (accf[0][j] - mean[0]) * rstd[0] * lw + lb;
        o0.y = (accf[1][j] - mean[1]) * rstd[1] * lw + lb;
        o0.z = (accf[2][j] - mean[2]) * rstd[2] * lw + lb;
        o0.w = (accf[3][j] - mean[3]) * rstd[3] * lw + lb;
        o1.x = (accf[4][j] - mean[4]) * rstd[4] * lw + lb;
        o1.y = (accf[5][j] - mean[5]) * rstd[5] * lw + lb;
        o1.z = (accf[6][j] - mean[6]) * rstd[6] * lw + lb;
        o1.w = (accf[7][j] - mean[7]) * rstd[7] * lw + lb;
        float* dst = out + ((size_t)(b * 128 + c)) * Pp + prowBase;
        *(float4*)dst = o0;
        *(float4*)(dst + 4) = o1;
    }
}

// ---------------------------------------------------------------
extern "C" void kernel_launch(void* const* d_in, const int* in_sizes, int n_in,
                              void* d_out, int out_size) {
    const float* query = (const float*)d_in[0];
    const float* ref   = (const float*)d_in[1];
    const float* homo  = (const float*)d_in[2];
    const float* ln1w  = (const float*)d_in[3];
    const float* ln1b  = (const float*)d_in[4];
    const float* ln2w  = (const float*)d_in[5];
    const float* ln2b  = (const float*)d_in[6];
    const float* w1    = (const float*)d_in[7];
    const float* b1    = (const float*)d_in[8];
    const float* w2    = (const float*)d_in[9];
    const float* b2    = (const float*)d_in[10];
    float* out = (float*)d_out;

    transpose_ref_h_kernel<<<dim3(Pp / 32, 1, Bb * Nn), 256>>>(ref);
    transpose_q_kernel<<<dim3(Pp / 32, Dd / 32, Bb), dim3(32, 8)>>>(query);
    attn_kernel<<<Mm / 8, 256>>>(homo, ln1w, ln1b);
    gemm1_kernel<<<dim3(Mm / 128, 2), 256>>>(w1, b1);
    gemm2_kernel<<<Mm / 128, 256>>>(w2, b2, ln2w, ln2b, out);
}

// round 6
// speedup vs baseline: 2.2087x; 1.9339x over previous
#include <cuda_runtime.h>
#include <cuda_fp16.h>
#include <math.h>
#include <stdint.h>

#define Pp 16384
#define Dd 128
#define Bb 4
#define Nn 6
#define Mm 65536   // B*P rows

// ---- scratch (static device globals; no allocation allowed) ----
__device__ __half  refTh_g[(size_t)Bb * Nn * Pp * Dd]; // (bn, p, d) fp16
__device__ float   qT_g[(size_t)Bb * Pp * Dd];         // (bp, d) fp32
__device__ float   ztLN_g[(size_t)Bb * Pp * Dd];       // (bp, d) fp32 (residual)
__device__ __half  ztLNh_g[(size_t)Mm * Dd];           // fp16 copy for GEMM1
__device__ __half  hbufh_g[(size_t)Mm * 256];          // gelu output fp16
__device__ __half  W1h_g[256 * 128];                   // [n][k] fp16
__device__ __half  W2h_g[128 * 256];                   // [n][k] fp16

// ---------------------------------------------------------------
// helpers
// ---------------------------------------------------------------
__device__ __forceinline__ float warpsum(float v) {
#pragma unroll
    for (int s = 16; s; s >>= 1) v += __shfl_xor_sync(0xffffffffu, v, s);
    return v;
}
__device__ __forceinline__ float gelu_exact(float x) {
    return 0.5f * x * (1.0f + erff(x * 0.70710678118654752440f));
}
__device__ __forceinline__ float4 ldg_half4(const __half* p) {
    uint2 u = *(const uint2*)p;
    __half2 h0 = *reinterpret_cast<__half2*>(&u.x);
    __half2 h1 = *reinterpret_cast<__half2*>(&u.y);
    float2 f0 = __half22float2(h0), f1 = __half22float2(h1);
    return make_float4(f0.x, f0.y, f1.x, f1.y);
}
__device__ __forceinline__ uint32_t smem_u32(const void* p) {
    uint32_t a;
    asm("{ .reg .u64 t; cvta.to.shared.u64 t, %1; cvt.u32.u64 %0, t; }" : "=r"(a) : "l"(p));
    return a;
}

#define LDSM_X4(r0, r1, r2, r3, a) \
    asm volatile("ldmatrix.sync.aligned.m8n8.x4.shared.b16 {%0,%1,%2,%3}, [%4];" \
                 : "=r"(r0), "=r"(r1), "=r"(r2), "=r"(r3) : "r"(a))
#define LDSM_X2(r0, r1, a) \
    asm volatile("ldmatrix.sync.aligned.m8n8.x2.shared.b16 {%0,%1}, [%2];" \
                 : "=r"(r0), "=r"(r1) : "r"(a))
#define MMA16816(d, a, b) \
    asm volatile("mma.sync.aligned.m16n8k16.row.col.f32.f16.f16.f32 " \
                 "{%0,%1,%2,%3}, {%4,%5,%6,%7}, {%8,%9}, {%0,%1,%2,%3};" \
                 : "+f"((d)[0]), "+f"((d)[1]), "+f"((d)[2]), "+f"((d)[3]) \
                 : "r"((a)[0]), "r"((a)[1]), "r"((a)[2]), "r"((a)[3]), \
                   "r"((b)[0]), "r"((b)[1]))

#define APITCH 136   // halves per smem row (128 + 8 pad -> conflict-free ldmatrix)

// ---------------------------------------------------------------
// Transpose ref (mat, D=128, P) -> fp16 (mat, P, D)
// ---------------------------------------------------------------
__global__ void __launch_bounds__(256) transpose_ref_h_kernel(const float* __restrict__ in) {
    __shared__ float tile[32][129];
    int mat = blockIdx.z;
    int p0 = blockIdx.x * 32;
    const float* src = in + (size_t)mat * Dd * Pp;
    __half* dst = refTh_g + (size_t)mat * Pp * Dd;

    int lane = threadIdx.x & 31;
    int ty = threadIdx.x >> 5;
#pragma unroll
    for (int it = 0; it < 16; it++) {
        int d = it * 8 + ty;
        tile[lane][d] = src[(size_t)d * Pp + p0 + lane];
    }
    __syncthreads();
    int pi = threadIdx.x & 63;
    int ppb = threadIdx.x >> 6;
#pragma unroll
    for (int it = 0; it < 8; it++) {
        int pp = it * 4 + ppb;
        float2 f = make_float2(tile[pp][2 * pi], tile[pp][2 * pi + 1]);
        *(__half2*)(dst + (size_t)(p0 + pp) * Dd + 2 * pi) = __float22half2_rn(f);
    }
}

// ---------------------------------------------------------------
// Transpose q (b, D=128, P) -> fp32 (b, P, D)
// ---------------------------------------------------------------
__global__ void transpose_q_kernel(const float* __restrict__ in) {
    __shared__ float tile[32][33];
    int mat = blockIdx.z;
    const float* src = in + (size_t)mat * Dd * Pp;
    float* dst = qT_g + (size_t)mat * Dd * Pp;
    int p0 = blockIdx.x * 32, d0 = blockIdx.y * 32;
#pragma unroll
    for (int i = threadIdx.y; i < 32; i += 8)
        tile[i][threadIdx.x] = src[(size_t)(d0 + i) * Pp + p0 + threadIdx.x];
    __syncthreads();
#pragma unroll
    for (int i = threadIdx.y; i < 32; i += 8)
        dst[(size_t)(p0 + i) * Dd + d0 + threadIdx.x] = tile[threadIdx.x][i];
}

// ---------------------------------------------------------------
// Weight prep: W1[128,256] -> W1h [n=256][k=128]; W2[256,128] -> W2h [n=128][k=256]
// ---------------------------------------------------------------
__global__ void prep_w1_kernel(const float* __restrict__ W1) {
    int idx = blockIdx.x * 256 + threadIdx.x;
    int n = idx >> 7, k = idx & 127;
    W1h_g[idx] = __float2half(W1[(size_t)k * 256 + n]);
}
__global__ void prep_w2_kernel(const float* __restrict__ W2) {
    int idx = blockIdx.x * 256 + threadIdx.x;
    int n = idx >> 8, k = idx & 255;
    W2h_g[idx] = __float2half(W2[(size_t)k * 128 + n]);
}

// ---------------------------------------------------------------
// Attention (unchanged from R4-passing version)
// ---------------------------------------------------------------
__global__ void __launch_bounds__(256) attn_kernel(const float* __restrict__ homo,
                                                   const float* __restrict__ ln1w,
                                                   const float* __restrict__ ln1b) {
    int lane = threadIdx.x & 31;
    int warp = threadIdx.x >> 5;
    int gp = blockIdx.x * 8 + warp;
    int b = gp >> 14;
    int p = gp & (Pp - 1);

    float4 qv = *(const float4*)(qT_g + (size_t)gp * Dd + lane * 4);
    float qn2 = warpsum(qv.x * qv.x + qv.y * qv.y + qv.z * qv.z + qv.w * qv.w);
    float qden = fmaxf(sqrtf(qn2), 1e-12f);

    float4 vals[6];
    float dots[6];

#pragma unroll
    for (int n = 0; n < 6; n++) {
        int bn = b * Nn + n;
        float u = homo[(size_t)(bn * 2 + 0) * Pp + p] * 128.0f;
        float v = homo[(size_t)(bn * 2 + 1) * Pp + p] * 128.0f;
        float wx = u - floorf(u), wy = v - floorf(v);
        int ix0 = min(max(__float2int_rd(u), 0), 127);
        int ix1 = min(max(__float2int_rd(u) + 1, 0), 127);
        int iy0 = min(max(__float2int_rd(v), 0), 127);
        int iy1 = min(max(__float2int_rd(v) + 1, 0), 127);
        bool valid = (u >= 0.0f) && (u <= 127.0f) && (v >= 0.0f) && (v <= 127.0f);

        const __half* base = refTh_g + (size_t)bn * Pp * Dd + lane * 4;
        float4 v00 = ldg_half4(base + (size_t)(iy0 * 128 + ix0) * Dd);
        float4 v10 = ldg_half4(base + (size_t)(iy0 * 128 + ix1) * Dd);
        float4 v01 = ldg_half4(base + (size_t)(iy1 * 128 + ix0) * Dd);
        float4 v11 = ldg_half4(base + (size_t)(iy1 * 128 + ix1) * Dd);

        float w00 = (1.0f - wx) * (1.0f - wy);
        float w10 = wx * (1.0f - wy);
        float w01 = (1.0f - wx) * wy;
        float w11 = wx * wy;

        float4 val;
        val.x = w00 * v00.x + w10 * v10.x + w01 * v01.x + w11 * v11.x;
        val.y = w00 * v00.y + w10 * v10.y + w01 * v01.y + w11 * v11.y;
        val.z = w00 * v00.z + w10 * v10.z + w01 * v01.z + w11 * v11.z;
        val.w = w00 * v00.w + w10 * v10.w + w01 * v01.w + w11 * v11.w;
        vals[n] = val;

        float v2 = val.x * val.x + val.y * val.y + val.z * val.z + val.w * val.w;
        float s  = qv.x * val.x + qv.y * val.y + qv.z * val.z + qv.w * val.w;
        v2 = warpsum(v2);
        s = warpsum(s);
        float vden = fmaxf(sqrtf(v2), 1e-12f);
        dots[n] = valid ? (s / (qden * vden)) : 0.0f;
    }

    float m = dots[0];
#pragma unroll
    for (int n = 1; n < 6; n++) m = fmaxf(m, dots[n]);
    float e[6], esum = 0.0f;
#pragma unroll
    for (int n = 0; n < 6; n++) { e[n] = expf(dots[n] - m); esum += e[n]; }
    float inv = 1.0f / esum;

    float zt[4];
    zt[0] = qv.x; zt[1] = qv.y; zt[2] = qv.z; zt[3] = qv.w;
#pragma unroll
    for (int k = 0; k < 4; k++) {
        float z = 0.0f;
#pragma unroll
        for (int n = 0; n < 6; n++) z += e[n] * ((const float*)&vals[n])[k];
        zt[k] += z * inv;
    }

    float mean = warpsum(zt[0] + zt[1] + zt[2] + zt[3]) * (1.0f / 128.0f);
    float dv = 0.0f;
#pragma unroll
    for (int k = 0; k < 4; k++) { float dd = zt[k] - mean; dv += dd * dd; }
    float rstd = rsqrtf(warpsum(dv) * (1.0f / 128.0f) + 1e-5f);

    float4 lw = *(const float4*)(ln1w + lane * 4);
    float4 lb = *(const float4*)(ln1b + lane * 4);
    float4 o;
    o.x = (zt[0] - mean) * rstd * lw.x + lb.x;
    o.y = (zt[1] - mean) * rstd * lw.y + lb.y;
    o.z = (zt[2] - mean) * rstd * lw.z + lb.z;
    o.w = (zt[3] - mean) * rstd * lw.w + lb.w;
    *(float4*)(ztLN_g + (size_t)gp * Dd + lane * 4) = o;

    __half2* dh = (__half2*)(ztLNh_g + (size_t)gp * Dd + lane * 4);
    dh[0] = __floats2half2_rn(o.x, o.y);
    dh[1] = __floats2half2_rn(o.z, o.w);
}

// ---------------------------------------------------------------
// GEMM1 (mma.sync): H = gelu(ztLNh @ W1 + b1). fp16 in, fp32 acc, fp16 out.
// CTA tile 128x128 (grid.y=2 covers N=256), K=128 single stage.
// 8 warps as 2x4; each warp 64x32 via m16n8k16 (4 mtiles x 4 ntiles).
// ---------------------------------------------------------------
#define G1_SMEM (2 * 128 * APITCH * 2)   // 69632 bytes
__global__ void __launch_bounds__(256) gemm1_mma(const float* __restrict__ b1) {
    extern __shared__ __half sm1[];
    __half* Ah = sm1;
    __half* Bh = sm1 + 128 * APITCH;
    uint32_t Abase = smem_u32(Ah), Bbase = smem_u32(Bh);

    int tid = threadIdx.x;
    int warp = tid >> 5, lane = tid & 31;
    int rowBase = blockIdx.x * 128;
    int colBase = blockIdx.y * 128;

    for (int idx = tid; idx < 2048; idx += 256) {
        int r = idx >> 4, kg = (idx & 15) << 3;
        *(float4*)(Ah + r * APITCH + kg) =
            *(const float4*)(ztLNh_g + (size_t)(rowBase + r) * 128 + kg);
        *(float4*)(Bh + r * APITCH + kg) =
            *(const float4*)(W1h_g + (size_t)(colBase + r) * 128 + kg);
    }
    __syncthreads();

    int warp_m = warp & 1, warp_n = warp >> 1;
    int rm = warp_m * 64, cn = warp_n * 32;
    int arow = (lane & 7) + ((lane >> 3) & 1) * 8;
    int akol = (lane >> 4) * 8;
    int brow = lane & 7;
    int bkol = ((lane >> 3) & 1) * 8;

    float acc[4][4][4] = {};
#pragma unroll
    for (int ks = 0; ks < 8; ks++) {
        int k0 = ks * 16;
        uint32_t a[4][4], bf[4][2];
#pragma unroll
        for (int mt = 0; mt < 4; mt++)
            LDSM_X4(a[mt][0], a[mt][1], a[mt][2], a[mt][3],
                    Abase + ((rm + mt * 16 + arow) * APITCH + k0 + akol) * 2);
#pragma unroll
        for (int nt = 0; nt < 4; nt++)
            LDSM_X2(bf[nt][0], bf[nt][1],
                    Bbase + ((cn + nt * 8 + brow) * APITCH + k0 + bkol) * 2);
#pragma unroll
        for (int mt = 0; mt < 4; mt++)
#pragma unroll
            for (int nt = 0; nt < 4; nt++)
                MMA16816(acc[mt][nt], a[mt], bf[nt]);
    }

    int qrow = lane >> 2, qcol = (lane & 3) * 2;
#pragma unroll
    for (int nt = 0; nt < 4; nt++) {
        int col = colBase + cn + nt * 8 + qcol;
        float bx = __ldg(b1 + col), by = __ldg(b1 + col + 1);
#pragma unroll
        for (int mt = 0; mt < 4; mt++) {
            int row = rowBase + rm + mt * 16 + qrow;
            __half2 h0 = __floats2half2_rn(gelu_exact(acc[mt][nt][0] + bx),
                                           gelu_exact(acc[mt][nt][1] + by));
            __half2 h1 = __floats2half2_rn(gelu_exact(acc[mt][nt][2] + bx),
                                           gelu_exact(acc[mt][nt][3] + by));
            *(__half2*)(hbufh_g + (size_t)row * 256 + col) = h0;
            *(__half2*)(hbufh_g + (size_t)(row + 8) * 256 + col) = h1;
        }
    }
}

// ---------------------------------------------------------------
// GEMM2 (mma.sync): zt2 = ztLN + hbufh @ W2 + b2; LN2; transposed store.
// CTA 128 rows x 128 cols (full N). K=256 in two staged chunks of 128.
// Cross-warp LN via smem partials; staged smem transpose for coalesced out.
// ---------------------------------------------------------------
#define G2_SMEM (2 * 128 * APITCH * 2 + 4096)   // 73728 bytes
__global__ void __launch_bounds__(256) gemm2_mma(const float* __restrict__ b2,
                                                 const float* __restrict__ ln2w,
                                                 const float* __restrict__ ln2b,
                                                 float* __restrict__ out) {
    extern __shared__ __half sm2[];
    __half* Ah = sm2;
    __half* Bh = sm2 + 128 * APITCH;
    float* redS = (float*)(sm2 + 2 * 128 * APITCH);          // [128][4]
    float* redQ = redS + 512;                                 // [128][4]
    float* stg  = (float*)sm2;                                // [128][132] reuse
    uint32_t Abase = smem_u32(Ah), Bbase = smem_u32(Bh);

    int tid = threadIdx.x;
    int warp = tid >> 5, lane = tid & 31;
    int rowBase = blockIdx.x * 128;

    int warp_m = warp & 1, warp_n = warp >> 1;
    int rm = warp_m * 64, cn = warp_n * 32;
    int arow = (lane & 7) + ((lane >> 3) & 1) * 8;
    int akol = (lane >> 4) * 8;
    int brow = lane & 7;
    int bkol = ((lane >> 3) & 1) * 8;

    float acc[4][4][4] = {};
#pragma unroll
    for (int kc = 0; kc < 2; kc++) {
        for (int idx = tid; idx < 2048; idx += 256) {
            int r = idx >> 4, kg = (idx & 15) << 3;
            *(float4*)(Ah + r * APITCH + kg) =
                *(const float4*)(hbufh_g + (size_t)(rowBase + r) * 256 + kc * 128 + kg);
            *(float4*)(Bh + r * APITCH + kg) =
                *(const float4*)(W2h_g + (size_t)r * 256 + kc * 128 + kg);
        }
        __syncthreads();
#pragma unroll
        for (int ks = 0; ks < 8; ks++) {
            int k0 = ks * 16;
            uint32_t a[4][4], bf[4][2];
#pragma unroll
            for (int mt = 0; mt < 4; mt++)
                LDSM_X4(a[mt][0], a[mt][1], a[mt][2], a[mt][3],
                        Abase + ((rm + mt * 16 + arow) * APITCH + k0 + akol) * 2);
#pragma unroll
            for (int nt = 0; nt < 4; nt++)
                LDSM_X2(bf[nt][0], bf[nt][1],
                        Bbase + ((cn + nt * 8 + brow) * APITCH + k0 + bkol) * 2);
#pragma unroll
            for (int mt = 0; mt < 4; mt++)
#pragma unroll
                for (int nt = 0; nt < 4; nt++)
                    MMA16816(acc[mt][nt], a[mt], bf[nt]);
        }
        __syncthreads();
    }

    int qrow = lane >> 2, qcol = (lane & 3) * 2;

    // add residual + bias; accumulate LN partials
#pragma unroll
    for (int mt = 0; mt < 4; mt++) {
        int rlo = rm + mt * 16 + qrow;        // local row
        int rhi = rlo + 8;
        float sLo = 0.0f, qLo = 0.0f, sHi = 0.0f, qHi = 0.0f;
#pragma unroll
        for (int nt = 0; nt < 4; nt++) {
            int col = cn + nt * 8 + qcol;
            float bx = __ldg(b2 + col), by = __ldg(b2 + col + 1);
            float2 zlo = *(const float2*)(ztLN_g + (size_t)(rowBase + rlo) * 128 + col);
            float2 zhi = *(const float2*)(ztLN_g + (size_t)(rowBase + rhi) * 128 + col);
            acc[mt][nt][0] += zlo.x + bx;
            acc[mt][nt][1] += zlo.y + by;
            acc[mt][nt][2] += zhi.x + bx;
            acc[mt][nt][3] += zhi.y + by;
            sLo += acc[mt][nt][0] + acc[mt][nt][1];
            qLo += acc[mt][nt][0] * acc[mt][nt][0] + acc[mt][nt][1] * acc[mt][nt][1];
            sHi += acc[mt][nt][2] + acc[mt][nt][3];
            qHi += acc[mt][nt][2] * acc[mt][nt][2] + acc[mt][nt][3] * acc[mt][nt][3];
        }
#pragma unroll
        for (int sh = 1; sh < 4; sh <<= 1) {
            sLo += __shfl_xor_sync(0xffffffffu, sLo, sh);
            qLo += __shfl_xor_sync(0xffffffffu, qLo, sh);
            sHi += __shfl_xor_sync(0xffffffffu, sHi, sh);
            qHi += __shfl_xor_sync(0xffffffffu, qHi, sh);
        }
        if ((lane & 3) == 0) {
            redS[rlo * 4 + warp_n] = sLo;
            redQ[rlo * 4 + warp_n] = qLo;
            redS[rhi * 4 + warp_n] = sHi;
            redQ[rhi * 4 + warp_n] = qHi;
        }
    }
    __syncthreads();

    // finalize LN per owned row and write to staging (transposed: stg[col][row])
#pragma unroll
    for (int mt = 0; mt < 4; mt++) {
        int rlo = rm + mt * 16 + qrow;
        int rhi = rlo + 8;
        float sLo = redS[rlo * 4 + 0] + redS[rlo * 4 + 1] + redS[rlo * 4 + 2] + redS[rlo * 4 + 3];
        float qLo = redQ[rlo * 4 + 0] + redQ[rlo * 4 + 1] + redQ[rlo * 4 + 2] + redQ[rlo * 4 + 3];
        float sHi = redS[rhi * 4 + 0] + redS[rhi * 4 + 1] + redS[rhi * 4 + 2] + redS[rhi * 4 + 3];
        float qHi = redQ[rhi * 4 + 0] + redQ[rhi * 4 + 1] + redQ[rhi * 4 + 2] + redQ[rhi * 4 + 3];
        float mLo = sLo * (1.0f / 128.0f);
        float rLo = rsqrtf(qLo * (1.0f / 128.0f) - mLo * mLo + 1e-5f);
        float mHi = sHi * (1.0f / 128.0f);
        float rHi = rsqrtf(qHi * (1.0f / 128.0f) - mHi * mHi + 1e-5f);
#pragma unroll
        for (int nt = 0; nt < 4; nt++) {
            int col = cn + nt * 8 + qcol;
            float lwx = __ldg(ln2w + col), lwy = __ldg(ln2w + col + 1);
            float lbx = __ldg(ln2b + col), lby = __ldg(ln2b + col + 1);
            stg[(col + 0) * 132 + rlo] = (acc[mt][nt][0] - mLo) * rLo * lwx + lbx;
            stg[(col + 1) * 132 + rlo] = (acc[mt][nt][1] - mLo) * rLo * lwy + lby;
            stg[(col + 0) * 132 + rhi] = (acc[mt][nt][2] - mHi) * rHi * lwx + lbx;
            stg[(col + 1) * 132 + rhi] = (acc[mt][nt][3] - mHi) * rHi * lwy + lby;
        }
    }
    __syncthreads();

    int b = rowBase >> 14;
    int prowBase = rowBase & (Pp - 1);
    for (int idx = tid; idx < 4096; idx += 256) {
        int c = idx >> 5;
        int j = (idx & 31) * 4;
        float4 v = *(const float4*)(stg + c * 132 + j);
        *(float4*)(out + ((size_t)(b * 128 + c)) * Pp + prowBase + j) = v;
    }
}

// ---------------------------------------------------------------
extern "C" void kernel_launch(void* const* d_in, const int* in_sizes, int n_in,
                              void* d_out, int out_size) {
    const float* query = (const float*)d_in[0];
    const float* ref   = (const float*)d_in[1];
    const float* homo  = (const float*)d_in[2];
    const float* ln1w  = (const float*)d_in[3];
    const float* ln1b  = (const float*)d_in[4];
    const float* ln2w  = (const float*)d_in[5];
    const float* ln2b  = (const float*)d_in[6];
    const float* w1    = (const float*)d_in[7];
    const float* b1    = (const float*)d_in[8];
    const float* w2    = (const float*)d_in[9];
    const float* b2    = (const float*)d_in[10];
    float* out = (float*)d_out;

    cudaFuncSetAttribute(gemm1_mma, cudaFuncAttributeMaxDynamicSharedMemorySize, G1_SMEM);
    cudaFuncSetAttribute(gemm2_mma, cudaFuncAttributeMaxDynamicSharedMemorySize, G2_SMEM);

    transpose_ref_h_kernel<<<dim3(Pp / 32, 1, Bb * Nn), 256>>>(ref);
    transpose_q_kernel<<<dim3(Pp / 32, Dd / 32, Bb), dim3(32, 8)>>>(query);
    prep_w1_kernel<<<128, 256>>>(w1);
    prep_w2_kernel<<<128, 256>>>(w2);
    attn_kernel<<<Mm / 8, 256>>>(homo, ln1w, ln1b);
    gemm1_mma<<<dim3(Mm / 128, 2), 256, G1_SMEM>>>(b1);
    gemm2_mma<<<Mm / 128, 256, G2_SMEM>>>(b2, ln2w, ln2b, out);
}

// round 7
// speedup vs baseline: 2.2817x; 1.0331x over previous
#include <cuda_runtime.h>
#include <cuda_fp16.h>
#include <math.h>
#include <stdint.h>

#define Pp 16384
#define Dd 128
#define Bb 4
#define Nn 6
#define Mm 65536   // B*P rows

// ---- scratch (static device globals; no allocation allowed) ----
__device__ __half  refTh_g[(size_t)Bb * Nn * Pp * Dd]; // (bn, p, d) fp16
__device__ float   qT_g[(size_t)Bb * Pp * Dd];         // (bp, d) fp32
__device__ float   ztLN_g[(size_t)Bb * Pp * Dd];       // (bp, d) fp32 (residual)
__device__ __half  ztLNh_g[(size_t)Mm * Dd];           // fp16 copy for GEMM1
__device__ __half  hbufh_g[(size_t)Mm * 256];          // gelu output fp16
__device__ __half  W1h_g[256 * 128];                   // [n][k] fp16
__device__ __half  W2h_g[128 * 256];                   // [n][k] fp16

// ---------------------------------------------------------------
// helpers
// ---------------------------------------------------------------
__device__ __forceinline__ float warpsum(float v) {
#pragma unroll
    for (int s = 16; s; s >>= 1) v += __shfl_xor_sync(0xffffffffu, v, s);
    return v;
}
__device__ __forceinline__ float gelu_exact(float x) {
    return 0.5f * x * (1.0f + erff(x * 0.70710678118654752440f));
}
__device__ __forceinline__ float4 ldg_half4(const __half* p) {
    uint2 u = *(const uint2*)p;
    __half2 h0 = *reinterpret_cast<__half2*>(&u.x);
    __half2 h1 = *reinterpret_cast<__half2*>(&u.y);
    float2 f0 = __half22float2(h0), f1 = __half22float2(h1);
    return make_float4(f0.x, f0.y, f1.x, f1.y);
}
__device__ __forceinline__ uint32_t smem_u32(const void* p) {
    uint32_t a;
    asm("{ .reg .u64 t; cvta.to.shared.u64 t, %1; cvt.u32.u64 %0, t; }" : "=r"(a) : "l"(p));
    return a;
}

#define LDSM_X4(r0, r1, r2, r3, a) \
    asm volatile("ldmatrix.sync.aligned.m8n8.x4.shared.b16 {%0,%1,%2,%3}, [%4];" \
                 : "=r"(r0), "=r"(r1), "=r"(r2), "=r"(r3) : "r"(a))
#define LDSM_X2(r0, r1, a) \
    asm volatile("ldmatrix.sync.aligned.m8n8.x2.shared.b16 {%0,%1}, [%2];" \
                 : "=r"(r0), "=r"(r1) : "r"(a))
#define MMA16816(d, a, b) \
    asm volatile("mma.sync.aligned.m16n8k16.row.col.f32.f16.f16.f32 " \
                 "{%0,%1,%2,%3}, {%4,%5,%6,%7}, {%8,%9}, {%0,%1,%2,%3};" \
                 : "+f"((d)[0]), "+f"((d)[1]), "+f"((d)[2]), "+f"((d)[3]) \
                 : "r"((a)[0]), "r"((a)[1]), "r"((a)[2]), "r"((a)[3]), \
                   "r"((b)[0]), "r"((b)[1]))

#define APITCH 136   // halves per smem row (128 + 8 pad -> conflict-free ldmatrix)

// ---------------------------------------------------------------
// Transpose ref (mat, D=128, P) -> fp16 (mat, P, D)
// ---------------------------------------------------------------
__global__ void __launch_bounds__(256) transpose_ref_h_kernel(const float* __restrict__ in) {
    __shared__ float tile[32][129];
    int mat = blockIdx.z;
    int p0 = blockIdx.x * 32;
    const float* src = in + (size_t)mat * Dd * Pp;
    __half* dst = refTh_g + (size_t)mat * Pp * Dd;

    int lane = threadIdx.x & 31;
    int ty = threadIdx.x >> 5;
#pragma unroll
    for (int it = 0; it < 16; it++) {
        int d = it * 8 + ty;
        tile[lane][d] = src[(size_t)d * Pp + p0 + lane];
    }
    __syncthreads();
    int pi = threadIdx.x & 63;
    int ppb = threadIdx.x >> 6;
#pragma unroll
    for (int it = 0; it < 8; it++) {
        int pp = it * 4 + ppb;
        float2 f = make_float2(tile[pp][2 * pi], tile[pp][2 * pi + 1]);
        *(__half2*)(dst + (size_t)(p0 + pp) * Dd + 2 * pi) = __float22half2_rn(f);
    }
}

// ---------------------------------------------------------------
// Transpose q (b, D=128, P) -> fp32 (b, P, D)
// ---------------------------------------------------------------
__global__ void transpose_q_kernel(const float* __restrict__ in) {
    __shared__ float tile[32][33];
    int mat = blockIdx.z;
    const float* src = in + (size_t)mat * Dd * Pp;
    float* dst = qT_g + (size_t)mat * Dd * Pp;
    int p0 = blockIdx.x * 32, d0 = blockIdx.y * 32;
#pragma unroll
    for (int i = threadIdx.y; i < 32; i += 8)
        tile[i][threadIdx.x] = src[(size_t)(d0 + i) * Pp + p0 + threadIdx.x];
    __syncthreads();
#pragma unroll
    for (int i = threadIdx.y; i < 32; i += 8)
        dst[(size_t)(p0 + i) * Dd + d0 + threadIdx.x] = tile[threadIdx.x][i];
}

// ---------------------------------------------------------------
// Weight prep (merged): W1[128,256]->W1h[n][k]; W2[256,128]->W2h[n][k]
// ---------------------------------------------------------------
__global__ void prep_w_kernel(const float* __restrict__ W1, const float* __restrict__ W2) {
    int idx = blockIdx.x * 256 + threadIdx.x;   // 0..65535
    if (idx < 32768) {
        int n = idx >> 7, k = idx & 127;
        W1h_g[idx] = __float2half(W1[(size_t)k * 256 + n]);
    } else {
        int j = idx - 32768;
        int n = j >> 8, k = j & 255;
        W2h_g[j] = __float2half(W2[(size_t)k * 128 + n]);
    }
}

// ---------------------------------------------------------------
// Attention: bilinear gather(fp16) + cosine dot + softmax(N=6) +
//            weighted sum + residual + LayerNorm1.
// ---------------------------------------------------------------
__global__ void __launch_bounds__(256) attn_kernel(const float* __restrict__ homo,
                                                   const float* __restrict__ ln1w,
                                                   const float* __restrict__ ln1b) {
    int lane = threadIdx.x & 31;
    int warp = threadIdx.x >> 5;
    int gp = blockIdx.x * 8 + warp;
    int b = gp >> 14;
    int p = gp & (Pp - 1);

    // hoist all homo loads (long-latency roots)
    float us[6], vs[6];
#pragma unroll
    for (int n = 0; n < 6; n++) {
        int bn = b * Nn + n;
        us[n] = homo[(size_t)(bn * 2 + 0) * Pp + p] * 128.0f;
        vs[n] = homo[(size_t)(bn * 2 + 1) * Pp + p] * 128.0f;
    }

    float4 qv = *(const float4*)(qT_g + (size_t)gp * Dd + lane * 4);
    float qn2 = warpsum(qv.x * qv.x + qv.y * qv.y + qv.z * qv.z + qv.w * qv.w);
    float qden = fmaxf(sqrtf(qn2), 1e-12f);

    float4 vals[6];
    float dots[6];

#pragma unroll
    for (int n = 0; n < 6; n++) {
        int bn = b * Nn + n;
        float u = us[n], v = vs[n];
        float wx = u - floorf(u), wy = v - floorf(v);
        int ix0 = min(max(__float2int_rd(u), 0), 127);
        int ix1 = min(max(__float2int_rd(u) + 1, 0), 127);
        int iy0 = min(max(__float2int_rd(v), 0), 127);
        int iy1 = min(max(__float2int_rd(v) + 1, 0), 127);
        bool valid = (u >= 0.0f) && (u <= 127.0f) && (v >= 0.0f) && (v <= 127.0f);

        const __half* base = refTh_g + (size_t)bn * Pp * Dd + lane * 4;
        float4 v00 = ldg_half4(base + (size_t)(iy0 * 128 + ix0) * Dd);
        float4 v10 = ldg_half4(base + (size_t)(iy0 * 128 + ix1) * Dd);
        float4 v01 = ldg_half4(base + (size_t)(iy1 * 128 + ix0) * Dd);
        float4 v11 = ldg_half4(base + (size_t)(iy1 * 128 + ix1) * Dd);

        float w00 = (1.0f - wx) * (1.0f - wy);
        float w10 = wx * (1.0f - wy);
        float w01 = (1.0f - wx) * wy;
        float w11 = wx * wy;

        float4 val;
        val.x = w00 * v00.x + w10 * v10.x + w01 * v01.x + w11 * v11.x;
        val.y = w00 * v00.y + w10 * v10.y + w01 * v01.y + w11 * v11.y;
        val.z = w00 * v00.z + w10 * v10.z + w01 * v01.z + w11 * v11.z;
        val.w = w00 * v00.w + w10 * v10.w + w01 * v01.w + w11 * v11.w;
        vals[n] = val;

        float v2 = val.x * val.x + val.y * val.y + val.z * val.z + val.w * val.w;
        float s  = qv.x * val.x + qv.y * val.y + qv.z * val.z + qv.w * val.w;
        v2 = warpsum(v2);
        s = warpsum(s);
        float vden = fmaxf(sqrtf(v2), 1e-12f);
        dots[n] = valid ? (s / (qden * vden)) : 0.0f;
    }

    float m = dots[0];
#pragma unroll
    for (int n = 1; n < 6; n++) m = fmaxf(m, dots[n]);
    float e[6], esum = 0.0f;
#pragma unroll
    for (int n = 0; n < 6; n++) { e[n] = expf(dots[n] - m); esum += e[n]; }
    float inv = 1.0f / esum;

    float zt[4];
    zt[0] = qv.x; zt[1] = qv.y; zt[2] = qv.z; zt[3] = qv.w;
#pragma unroll
    for (int k = 0; k < 4; k++) {
        float z = 0.0f;
#pragma unroll
        for (int n = 0; n < 6; n++) z += e[n] * ((const float*)&vals[n])[k];
        zt[k] += z * inv;
    }

    float mean = warpsum(zt[0] + zt[1] + zt[2] + zt[3]) * (1.0f / 128.0f);
    float dv = 0.0f;
#pragma unroll
    for (int k = 0; k < 4; k++) { float dd = zt[k] - mean; dv += dd * dd; }
    float rstd = rsqrtf(warpsum(dv) * (1.0f / 128.0f) + 1e-5f);

    float4 lw = *(const float4*)(ln1w + lane * 4);
    float4 lb = *(const float4*)(ln1b + lane * 4);
    float4 o;
    o.x = (zt[0] - mean) * rstd * lw.x + lb.x;
    o.y = (zt[1] - mean) * rstd * lw.y + lb.y;
    o.z = (zt[2] - mean) * rstd * lw.z + lb.z;
    o.w = (zt[3] - mean) * rstd * lw.w + lb.w;
    *(float4*)(ztLN_g + (size_t)gp * Dd + lane * 4) = o;

    __half2* dh = (__half2*)(ztLNh_g + (size_t)gp * Dd + lane * 4);
    dh[0] = __floats2half2_rn(o.x, o.y);
    dh[1] = __floats2half2_rn(o.z, o.w);
}

// ---------------------------------------------------------------
// GEMM1 (mma.sync): H = gelu(ztLNh @ W1 + b1). A loaded ONCE per CTA,
// full N=256 in smem, two column-halves computed serially from same A.
// ---------------------------------------------------------------
#define G1_SMEM (128 * APITCH * 2 + 256 * APITCH * 2)   // 104448
__global__ void __launch_bounds__(256) gemm1_mma(const float* __restrict__ b1) {
    extern __shared__ __half sm1[];
    __half* Ah = sm1;                      // 128 x APITCH
    __half* Bh = sm1 + 128 * APITCH;       // 256 x APITCH
    uint32_t Abase = smem_u32(Ah), Bbase = smem_u32(Bh);

    int tid = threadIdx.x;
    int warp = tid >> 5, lane = tid & 31;
    int rowBase = blockIdx.x * 128;

    for (int idx = tid; idx < 2048; idx += 256) {
        int r = idx >> 4, kg = (idx & 15) << 3;
        *(float4*)(Ah + r * APITCH + kg) =
            *(const float4*)(ztLNh_g + (size_t)(rowBase + r) * 128 + kg);
    }
    for (int idx = tid; idx < 4096; idx += 256) {
        int r = idx >> 4, kg = (idx & 15) << 3;
        *(float4*)(Bh + r * APITCH + kg) =
            *(const float4*)(W1h_g + (size_t)r * 128 + kg);
    }
    __syncthreads();

    int warp_m = warp & 1, warp_n = warp >> 1;
    int rm = warp_m * 64;
    int arow = (lane & 7) + ((lane >> 3) & 1) * 8;
    int akol = (lane >> 4) * 8;
    int brow = lane & 7;
    int bkol = ((lane >> 3) & 1) * 8;
    int qrow = lane >> 2, qcol = (lane & 3) * 2;

#pragma unroll
    for (int nh = 0; nh < 2; nh++) {
        int cn = nh * 128 + warp_n * 32;
        float acc[4][4][4] = {};
#pragma unroll
        for (int ks = 0; ks < 8; ks++) {
            int k0 = ks * 16;
            uint32_t a[4][4], bf[4][2];
#pragma unroll
            for (int mt = 0; mt < 4; mt++)
                LDSM_X4(a[mt][0], a[mt][1], a[mt][2], a[mt][3],
                        Abase + ((rm + mt * 16 + arow) * APITCH + k0 + akol) * 2);
#pragma unroll
            for (int nt = 0; nt < 4; nt++)
                LDSM_X2(bf[nt][0], bf[nt][1],
                        Bbase + ((cn + nt * 8 + brow) * APITCH + k0 + bkol) * 2);
#pragma unroll
            for (int mt = 0; mt < 4; mt++)
#pragma unroll
                for (int nt = 0; nt < 4; nt++)
                    MMA16816(acc[mt][nt], a[mt], bf[nt]);
        }

#pragma unroll
        for (int nt = 0; nt < 4; nt++) {
            int col = cn + nt * 8 + qcol;
            float bx = __ldg(b1 + col), by = __ldg(b1 + col + 1);
#pragma unroll
            for (int mt = 0; mt < 4; mt++) {
                int row = rowBase + rm + mt * 16 + qrow;
                __half2 h0 = __floats2half2_rn(gelu_exact(acc[mt][nt][0] + bx),
                                               gelu_exact(acc[mt][nt][1] + by));
                __half2 h1 = __floats2half2_rn(gelu_exact(acc[mt][nt][2] + bx),
                                               gelu_exact(acc[mt][nt][3] + by));
                *(__half2*)(hbufh_g + (size_t)row * 256 + col) = h0;
                *(__half2*)(hbufh_g + (size_t)(row + 8) * 256 + col) = h1;
            }
        }
    }
}

// ---------------------------------------------------------------
// GEMM2 (mma.sync): zt2 = ztLN + hbufh @ W2 + b2; LN2; transposed store.
// B (both K-chunks) resident in smem; A chunk-2 prefetched into registers
// during chunk-1 compute. Cross-warp LN via smem; staged transposed store.
// ---------------------------------------------------------------
#define G2A_OFF   0
#define G2B0_OFF  (128 * APITCH)
#define G2B1_OFF  (256 * APITCH)
#define G2RED_OFF (384 * APITCH)                // float area after 3 tiles
#define G2_SMEM   (384 * APITCH * 2 + 4096)     // 108544 bytes
__global__ void __launch_bounds__(256) gemm2_mma(const float* __restrict__ b2,
                                                 const float* __restrict__ ln2w,
                                                 const float* __restrict__ ln2b,
                                                 float* __restrict__ out) {
    extern __shared__ __half sm2[];
    __half* Ah  = sm2 + G2A_OFF;
    __half* Bh0 = sm2 + G2B0_OFF;
    __half* Bh1 = sm2 + G2B1_OFF;
    float* redS = (float*)(sm2 + G2RED_OFF);      // [128][4]
    float* redQ = redS + 512;                     // [128][4]
    float* stg  = (float*)sm2;                    // [128][132] reuse (67.6KB)
    uint32_t Abase = smem_u32(Ah);
    uint32_t Bbase0 = smem_u32(Bh0), Bbase1 = smem_u32(Bh1);

    int tid = threadIdx.x;
    int warp = tid >> 5, lane = tid & 31;
    int rowBase = blockIdx.x * 128;

    // load A chunk0 + both B chunks
    for (int idx = tid; idx < 2048; idx += 256) {
        int r = idx >> 4, kg = (idx & 15) << 3;
        *(float4*)(Ah + r * APITCH + kg) =
            *(const float4*)(hbufh_g + (size_t)(rowBase + r) * 256 + kg);
        *(float4*)(Bh0 + r * APITCH + kg) =
            *(const float4*)(W2h_g + (size_t)r * 256 + kg);
        *(float4*)(Bh1 + r * APITCH + kg) =
            *(const float4*)(W2h_g + (size_t)r * 256 + 128 + kg);
    }
    // prefetch A chunk1 into registers (overlaps with chunk0 compute)
    float4 pref[8];
#pragma unroll
    for (int t = 0; t < 8; t++) {
        int idx = tid + t * 256;
        int r = idx >> 4, kg = (idx & 15) << 3;
        pref[t] = *(const float4*)(hbufh_g + (size_t)(rowBase + r) * 256 + 128 + kg);
    }
    __syncthreads();

    int warp_m = warp & 1, warp_n = warp >> 1;
    int rm = warp_m * 64, cn = warp_n * 32;
    int arow = (lane & 7) + ((lane >> 3) & 1) * 8;
    int akol = (lane >> 4) * 8;
    int brow = lane & 7;
    int bkol = ((lane >> 3) & 1) * 8;

    float acc[4][4][4] = {};
#pragma unroll
    for (int kc = 0; kc < 2; kc++) {
        uint32_t Bb_ = kc ? Bbase1 : Bbase0;
#pragma unroll
        for (int ks = 0; ks < 8; ks++) {
            int k0 = ks * 16;
            uint32_t a[4][4], bf[4][2];
#pragma unroll
            for (int mt = 0; mt < 4; mt++)
                LDSM_X4(a[mt][0], a[mt][1], a[mt][2], a[mt][3],
                        Abase + ((rm + mt * 16 + arow) * APITCH + k0 + akol) * 2);
#pragma unroll
            for (int nt = 0; nt < 4; nt++)
                LDSM_X2(bf[nt][0], bf[nt][1],
                        Bb_ + ((cn + nt * 8 + brow) * APITCH + k0 + bkol) * 2);
#pragma unroll
            for (int mt = 0; mt < 4; mt++)
#pragma unroll
                for (int nt = 0; nt < 4; nt++)
                    MMA16816(acc[mt][nt], a[mt], bf[nt]);
        }
        if (kc == 0) {
            __syncthreads();   // done reading A chunk0
#pragma unroll
            for (int t = 0; t < 8; t++) {
                int idx = tid + t * 256;
                int r = idx >> 4, kg = (idx & 15) << 3;
                *(float4*)(Ah + r * APITCH + kg) = pref[t];
            }
            __syncthreads();
        }
    }

    int qrow = lane >> 2, qcol = (lane & 3) * 2;

    // residual + bias; LN partials
#pragma unroll
    for (int mt = 0; mt < 4; mt++) {
        int rlo = rm + mt * 16 + qrow;
        int rhi = rlo + 8;
        float sLo = 0.0f, qLo = 0.0f, sHi = 0.0f, qHi = 0.0f;
#pragma unroll
        for (int nt = 0; nt < 4; nt++) {
            int col = cn + nt * 8 + qcol;
            float bx = __ldg(b2 + col), by = __ldg(b2 + col + 1);
            float2 zlo = *(const float2*)(ztLN_g + (size_t)(rowBase + rlo) * 128 + col);
            float2 zhi = *(const float2*)(ztLN_g + (size_t)(rowBase + rhi) * 128 + col);
            acc[mt][nt][0] += zlo.x + bx;
            acc[mt][nt][1] += zlo.y + by;
            acc[mt][nt][2] += zhi.x + bx;
            acc[mt][nt][3] += zhi.y + by;
            sLo += acc[mt][nt][0] + acc[mt][nt][1];
            qLo += acc[mt][nt][0] * acc[mt][nt][0] + acc[mt][nt][1] * acc[mt][nt][1];
            sHi += acc[mt][nt][2] + acc[mt][nt][3];
            qHi += acc[mt][nt][2] * acc[mt][nt][2] + acc[mt][nt][3] * acc[mt][nt][3];
        }
#pragma unroll
        for (int sh = 1; sh < 4; sh <<= 1) {
            sLo += __shfl_xor_sync(0xffffffffu, sLo, sh);
            qLo += __shfl_xor_sync(0xffffffffu, qLo, sh);
            sHi += __shfl_xor_sync(0xffffffffu, sHi, sh);
            qHi += __shfl_xor_sync(0xffffffffu, qHi, sh);
        }
        if ((lane & 3) == 0) {
            redS[rlo * 4 + warp_n] = sLo;
            redQ[rlo * 4 + warp_n] = qLo;
            redS[rhi * 4 + warp_n] = sHi;
            redQ[rhi * 4 + warp_n] = qHi;
        }
    }
    __syncthreads();

    // finalize LN per row, write transposed staging stg[col][row]
#pragma unroll
    for (int mt = 0; mt < 4; mt++) {
        int rlo = rm + mt * 16 + qrow;
        int rhi = rlo + 8;
        float sLo = redS[rlo * 4 + 0] + redS[rlo * 4 + 1] + redS[rlo * 4 + 2] + redS[rlo * 4 + 3];
        float qLo = redQ[rlo * 4 + 0] + redQ[rlo * 4 + 1] + redQ[rlo * 4 + 2] + redQ[rlo * 4 + 3];
        float sHi = redS[rhi * 4 + 0] + redS[rhi * 4 + 1] + redS[rhi * 4 + 2] + redS[rhi * 4 + 3];
        float qHi = redQ[rhi * 4 + 0] + redQ[rhi * 4 + 1] + redQ[rhi * 4 + 2] + redQ[rhi * 4 + 3];
        float mLo = sLo * (1.0f / 128.0f);
        float rLo = rsqrtf(qLo * (1.0f / 128.0f) - mLo * mLo + 1e-5f);
        float mHi = sHi * (1.0f / 128.0f);
        float rHi = rsqrtf(qHi * (1.0f / 128.0f) - mHi * mHi + 1e-5f);
#pragma unroll
        for (int nt = 0; nt < 4; nt++) {
            int col = cn + nt * 8 + qcol;
            float lwx = __ldg(ln2w + col), lwy = __ldg(ln2w + col + 1);
            float lbx = __ldg(ln2b + col), lby = __ldg(ln2b + col + 1);
            stg[(col + 0) * 132 + rlo] = (acc[mt][nt][0] - mLo) * rLo * lwx + lbx;
            stg[(col + 1) * 132 + rlo] = (acc[mt][nt][1] - mLo) * rLo * lwy + lby;
            stg[(col + 0) * 132 + rhi] = (acc[mt][nt][2] - mHi) * rHi * lwx + lbx;
            stg[(col + 1) * 132 + rhi] = (acc[mt][nt][3] - mHi) * rHi * lwy + lby;
        }
    }
    __syncthreads();

    int b = rowBase >> 14;
    int prowBase = rowBase & (Pp - 1);
    for (int idx = tid; idx < 4096; idx += 256) {
        int c = idx >> 5;
        int j = (idx & 31) * 4;
        float4 v = *(const float4*)(stg + c * 132 + j);
        *(float4*)(out + ((size_t)(b * 128 + c)) * Pp + prowBase + j) = v;
    }
}

// ---------------------------------------------------------------
extern "C" void kernel_launch(void* const* d_in, const int* in_sizes, int n_in,
                              void* d_out, int out_size) {
    const float* query = (const float*)d_in[0];
    const float* ref   = (const float*)d_in[1];
    const float* homo  = (const float*)d_in[2];
    const float* ln1w  = (const float*)d_in[3];
    const float* ln1b  = (const float*)d_in[4];
    const float* ln2w  = (const float*)d_in[5];
    const float* ln2b  = (const float*)d_in[6];
    const float* w1    = (const float*)d_in[7];
    const float* b1    = (const float*)d_in[8];
    const float* w2    = (const float*)d_in[9];
    const float* b2    = (const float*)d_in[10];
    float* out = (float*)d_out;

    cudaFuncSetAttribute(gemm1_mma, cudaFuncAttributeMaxDynamicSharedMemorySize, G1_SMEM);
    cudaFuncSetAttribute(gemm2_mma, cudaFuncAttributeMaxDynamicSharedMemorySize, G2_SMEM);

    transpose_ref_h_kernel<<<dim3(Pp / 32, 1, Bb * Nn), 256>>>(ref);
    transpose_q_kernel<<<dim3(Pp / 32, Dd / 32, Bb), dim3(32, 8)>>>(query);
    prep_w_kernel<<<256, 256>>>(w1, w2);
    attn_kernel<<<Mm / 8, 256>>>(homo, ln1w, ln1b);
    gemm1_mma<<<Mm / 128, 256, G1_SMEM>>>(b1);
    gemm2_mma<<<Mm / 128, 256, G2_SMEM>>>(b2, ln2w, ln2b, out);
}

// round 8
// speedup vs baseline: 2.3944x; 1.0494x over previous
#include <cuda_runtime.h>
#include <cuda_fp16.h>
#include <math.h>
#include <stdint.h>

#define Pp 16384
#define Dd 128
#define Bb 4
#define Nn 6
#define Mm 65536   // B*P rows

// ---- scratch (static device globals; no allocation allowed) ----
__device__ __half  refTh_g[(size_t)Bb * Nn * Pp * Dd]; // (bn, p, d) fp16
__device__ float   qT_g[(size_t)Bb * Pp * Dd];         // (bp, d) fp32
__device__ float   ztLN_g[(size_t)Bb * Pp * Dd];       // (bp, d) fp32 (residual)
__device__ __half  ztLNh_g[(size_t)Mm * Dd];           // fp16 copy for GEMM1
__device__ __half  hbufh_g[(size_t)Mm * 256];          // gelu output fp16
__device__ __half  W1h_g[256 * 128];                   // [n][k] fp16
__device__ __half  W2h_g[128 * 256];                   // [n][k] fp16

// ---------------------------------------------------------------
// helpers
// ---------------------------------------------------------------
__device__ __forceinline__ float wsum16(float v) {
#pragma unroll
    for (int s = 1; s < 16; s <<= 1) v += __shfl_xor_sync(0xffffffffu, v, s);
    return v;
}
__device__ __forceinline__ float gelu_exact(float x) {
    return 0.5f * x * (1.0f + erff(x * 0.70710678118654752440f));
}
__device__ __forceinline__ void h8_to_f8(uint4 u, float* f) {
    float2 t;
    t = __half22float2(*reinterpret_cast<__half2*>(&u.x)); f[0] = t.x; f[1] = t.y;
    t = __half22float2(*reinterpret_cast<__half2*>(&u.y)); f[2] = t.x; f[3] = t.y;
    t = __half22float2(*reinterpret_cast<__half2*>(&u.z)); f[4] = t.x; f[5] = t.y;
    t = __half22float2(*reinterpret_cast<__half2*>(&u.w)); f[6] = t.x; f[7] = t.y;
}
__device__ __forceinline__ uint32_t smem_u32(const void* p) {
    uint32_t a;
    asm("{ .reg .u64 t; cvta.to.shared.u64 t, %1; cvt.u32.u64 %0, t; }" : "=r"(a) : "l"(p));
    return a;
}

#define LDSM_X4(r0, r1, r2, r3, a) \
    asm volatile("ldmatrix.sync.aligned.m8n8.x4.shared.b16 {%0,%1,%2,%3}, [%4];" \
                 : "=r"(r0), "=r"(r1), "=r"(r2), "=r"(r3) : "r"(a))
#define LDSM_X2(r0, r1, a) \
    asm volatile("ldmatrix.sync.aligned.m8n8.x2.shared.b16 {%0,%1}, [%2];" \
                 : "=r"(r0), "=r"(r1) : "r"(a))
#define MMA16816(d, a, b) \
    asm volatile("mma.sync.aligned.m16n8k16.row.col.f32.f16.f16.f32 " \
                 "{%0,%1,%2,%3}, {%4,%5,%6,%7}, {%8,%9}, {%0,%1,%2,%3};" \
                 : "+f"((d)[0]), "+f"((d)[1]), "+f"((d)[2]), "+f"((d)[3]) \
                 : "r"((a)[0]), "r"((a)[1]), "r"((a)[2]), "r"((a)[3]), \
                   "r"((b)[0]), "r"((b)[1]))

#define APITCH 136   // halves per smem row (128 + 8 pad -> conflict-free ldmatrix)

// ---------------------------------------------------------------
// Transpose ref (mat, D=128, P) -> fp16 (mat, P, D)
// ---------------------------------------------------------------
__global__ void __launch_bounds__(256) transpose_ref_h_kernel(const float* __restrict__ in) {
    __shared__ float tile[32][129];
    int mat = blockIdx.z;
    int p0 = blockIdx.x * 32;
    const float* src = in + (size_t)mat * Dd * Pp;
    __half* dst = refTh_g + (size_t)mat * Pp * Dd;

    int lane = threadIdx.x & 31;
    int ty = threadIdx.x >> 5;
#pragma unroll
    for (int it = 0; it < 16; it++) {
        int d = it * 8 + ty;
        tile[lane][d] = src[(size_t)d * Pp + p0 + lane];
    }
    __syncthreads();
    int pi = threadIdx.x & 63;
    int ppb = threadIdx.x >> 6;
#pragma unroll
    for (int it = 0; it < 8; it++) {
        int pp = it * 4 + ppb;
        float2 f = make_float2(tile[pp][2 * pi], tile[pp][2 * pi + 1]);
        *(__half2*)(dst + (size_t)(p0 + pp) * Dd + 2 * pi) = __float22half2_rn(f);
    }
}

// ---------------------------------------------------------------
// Transpose q (b, D=128, P) -> fp32 (b, P, D)
// ---------------------------------------------------------------
__global__ void transpose_q_kernel(const float* __restrict__ in) {
    __shared__ float tile[32][33];
    int mat = blockIdx.z;
    const float* src = in + (size_t)mat * Dd * Pp;
    float* dst = qT_g + (size_t)mat * Dd * Pp;
    int p0 = blockIdx.x * 32, d0 = blockIdx.y * 32;
#pragma unroll
    for (int i = threadIdx.y; i < 32; i += 8)
        tile[i][threadIdx.x] = src[(size_t)(d0 + i) * Pp + p0 + threadIdx.x];
    __syncthreads();
#pragma unroll
    for (int i = threadIdx.y; i < 32; i += 8)
        dst[(size_t)(p0 + i) * Dd + d0 + threadIdx.x] = tile[threadIdx.x][i];
}

// ---------------------------------------------------------------
// Weight prep (merged)
// ---------------------------------------------------------------
__global__ void prep_w_kernel(const float* __restrict__ W1, const float* __restrict__ W2) {
    int idx = blockIdx.x * 256 + threadIdx.x;   // 0..65535
    if (idx < 32768) {
        int n = idx >> 7, k = idx & 127;
        W1h_g[idx] = __float2half(W1[(size_t)k * 256 + n]);
    } else {
        int j = idx - 32768;
        int n = j >> 8, k = j & 255;
        W2h_g[j] = __float2half(W2[(size_t)k * 128 + n]);
    }
}

// ---------------------------------------------------------------
// Attention: 2 pixels per warp, 16 lanes per pixel, 8 channels per lane.
// Bilinear gather(fp16, 16B loads) + cosine dot + softmax(N=6) +
// weighted sum + residual + LayerNorm1.
// ---------------------------------------------------------------
__global__ void __launch_bounds__(256) attn_kernel(const float* __restrict__ homo,
                                                   const float* __restrict__ ln1w,
                                                   const float* __restrict__ ln1b) {
    int lane = threadIdx.x & 31;
    int warp = threadIdx.x >> 5;
    int sub = lane >> 4;           // pixel within warp (0/1)
    int sl = lane & 15;            // lane within 16-lane group
    int gp = blockIdx.x * 16 + warp * 2 + sub;
    int b = gp >> 14;
    int p = gp & (Pp - 1);

    // hoist homo loads
    float us[6], vs[6];
#pragma unroll
    for (int n = 0; n < 6; n++) {
        int bn = b * Nn + n;
        us[n] = homo[(size_t)(bn * 2 + 0) * Pp + p] * 128.0f;
        vs[n] = homo[(size_t)(bn * 2 + 1) * Pp + p] * 128.0f;
    }

    float q[8];
    {
        float4 q0 = *(const float4*)(qT_g + (size_t)gp * Dd + sl * 8);
        float4 q1 = *(const float4*)(qT_g + (size_t)gp * Dd + sl * 8 + 4);
        q[0] = q0.x; q[1] = q0.y; q[2] = q0.z; q[3] = q0.w;
        q[4] = q1.x; q[5] = q1.y; q[6] = q1.z; q[7] = q1.w;
    }
    float qn2 = 0.0f;
#pragma unroll
    for (int k = 0; k < 8; k++) qn2 += q[k] * q[k];
    qn2 = wsum16(qn2);
    float qden = fmaxf(sqrtf(qn2), 1e-12f);

    float vals[6][8];
    float dots[6];

#pragma unroll
    for (int n = 0; n < 6; n++) {
        int bn = b * Nn + n;
        float u = us[n], v = vs[n];
        float wx = u - floorf(u), wy = v - floorf(v);
        int ix0 = min(max(__float2int_rd(u), 0), 127);
        int ix1 = min(max(__float2int_rd(u) + 1, 0), 127);
        int iy0 = min(max(__float2int_rd(v), 0), 127);
        int iy1 = min(max(__float2int_rd(v) + 1, 0), 127);
        bool valid = (u >= 0.0f) && (u <= 127.0f) && (v >= 0.0f) && (v <= 127.0f);

        const __half* base = refTh_g + (size_t)bn * Pp * Dd + sl * 8;
        uint4 r00 = *(const uint4*)(base + ((iy0 << 7) + ix0) * Dd);
        uint4 r10 = *(const uint4*)(base + ((iy0 << 7) + ix1) * Dd);
        uint4 r01 = *(const uint4*)(base + ((iy1 << 7) + ix0) * Dd);
        uint4 r11 = *(const uint4*)(base + ((iy1 << 7) + ix1) * Dd);

        float c00[8], c10[8], c01[8], c11[8];
        h8_to_f8(r00, c00); h8_to_f8(r10, c10);
        h8_to_f8(r01, c01); h8_to_f8(r11, c11);

        float w00 = (1.0f - wx) * (1.0f - wy);
        float w10 = wx * (1.0f - wy);
        float w01 = (1.0f - wx) * wy;
        float w11 = wx * wy;

        float v2 = 0.0f, s = 0.0f;
#pragma unroll
        for (int k = 0; k < 8; k++) {
            float val = w00 * c00[k] + w10 * c10[k] + w01 * c01[k] + w11 * c11[k];
            vals[n][k] = val;
            v2 += val * val;
            s += q[k] * val;
        }
        v2 = wsum16(v2);
        s = wsum16(s);
        float vden = fmaxf(sqrtf(v2), 1e-12f);
        dots[n] = valid ? __fdividef(s, qden * vden) : 0.0f;
    }

    float m = dots[0];
#pragma unroll
    for (int n = 1; n < 6; n++) m = fmaxf(m, dots[n]);
    float e[6], esum = 0.0f;
#pragma unroll
    for (int n = 0; n < 6; n++) { e[n] = __expf(dots[n] - m); esum += e[n]; }
    float inv = __fdividef(1.0f, esum);

    float zt[8];
#pragma unroll
    for (int k = 0; k < 8; k++) {
        float z = 0.0f;
#pragma unroll
        for (int n = 0; n < 6; n++) z += e[n] * vals[n][k];
        zt[k] = q[k] + z * inv;
    }

    float ssum = 0.0f;
#pragma unroll
    for (int k = 0; k < 8; k++) ssum += zt[k];
    float mean = wsum16(ssum) * (1.0f / 128.0f);
    float dv = 0.0f;
#pragma unroll
    for (int k = 0; k < 8; k++) { float dd = zt[k] - mean; dv += dd * dd; }
    float rstd = rsqrtf(wsum16(dv) * (1.0f / 128.0f) + 1e-5f);

    float o[8];
    {
        float4 lw0 = *(const float4*)(ln1w + sl * 8);
        float4 lw1 = *(const float4*)(ln1w + sl * 8 + 4);
        float4 lb0 = *(const float4*)(ln1b + sl * 8);
        float4 lb1 = *(const float4*)(ln1b + sl * 8 + 4);
        const float* lwp = (const float*)&lw0;  // contiguous on stack? avoid — do explicit
        o[0] = (zt[0] - mean) * rstd * lw0.x + lb0.x;
        o[1] = (zt[1] - mean) * rstd * lw0.y + lb0.y;
        o[2] = (zt[2] - mean) * rstd * lw0.z + lb0.z;
        o[3] = (zt[3] - mean) * rstd * lw0.w + lb0.w;
        o[4] = (zt[4] - mean) * rstd * lw1.x + lb1.x;
        o[5] = (zt[5] - mean) * rstd * lw1.y + lb1.y;
        o[6] = (zt[6] - mean) * rstd * lw1.z + lb1.z;
        o[7] = (zt[7] - mean) * rstd * lw1.w + lb1.w;
        (void)lwp;
    }
    float* dstf = ztLN_g + (size_t)gp * Dd + sl * 8;
    *(float4*)dstf = make_float4(o[0], o[1], o[2], o[3]);
    *(float4*)(dstf + 4) = make_float4(o[4], o[5], o[6], o[7]);

    __half2 h[4];
    h[0] = __floats2half2_rn(o[0], o[1]);
    h[1] = __floats2half2_rn(o[2], o[3]);
    h[2] = __floats2half2_rn(o[4], o[5]);
    h[3] = __floats2half2_rn(o[6], o[7]);
    *(float4*)(ztLNh_g + (size_t)gp * Dd + sl * 8) = *(float4*)h;
}

// ---------------------------------------------------------------
// GEMM1 (mma.sync): H = gelu(ztLNh @ W1 + b1). A loaded once per CTA,
// full N=256 in smem, two column-halves computed serially from same A.
// ---------------------------------------------------------------
#define G1_SMEM (128 * APITCH * 2 + 256 * APITCH * 2)   // 104448
__global__ void __launch_bounds__(256) gemm1_mma(const float* __restrict__ b1) {
    extern __shared__ __half sm1[];
    __half* Ah = sm1;                      // 128 x APITCH
    __half* Bh = sm1 + 128 * APITCH;       // 256 x APITCH
    uint32_t Abase = smem_u32(Ah), Bbase = smem_u32(Bh);

    int tid = threadIdx.x;
    int warp = tid >> 5, lane = tid & 31;
    int rowBase = blockIdx.x * 128;

    for (int idx = tid; idx < 2048; idx += 256) {
        int r = idx >> 4, kg = (idx & 15) << 3;
        *(float4*)(Ah + r * APITCH + kg) =
            *(const float4*)(ztLNh_g + (size_t)(rowBase + r) * 128 + kg);
    }
    for (int idx = tid; idx < 4096; idx += 256) {
        int r = idx >> 4, kg = (idx & 15) << 3;
        *(float4*)(Bh + r * APITCH + kg) =
            *(const float4*)(W1h_g + (size_t)r * 128 + kg);
    }
    __syncthreads();

    int warp_m = warp & 1, warp_n = warp >> 1;
    int rm = warp_m * 64;
    int arow = (lane & 7) + ((lane >> 3) & 1) * 8;
    int akol = (lane >> 4) * 8;
    int brow = lane & 7;
    int bkol = ((lane >> 3) & 1) * 8;
    int qrow = lane >> 2, qcol = (lane & 3) * 2;

#pragma unroll
    for (int nh = 0; nh < 2; nh++) {
        int cn = nh * 128 + warp_n * 32;
        float acc[4][4][4] = {};
#pragma unroll
        for (int ks = 0; ks < 8; ks++) {
            int k0 = ks * 16;
            uint32_t a[4][4], bf[4][2];
#pragma unroll
            for (int mt = 0; mt < 4; mt++)
                LDSM_X4(a[mt][0], a[mt][1], a[mt][2], a[mt][3],
                        Abase + ((rm + mt * 16 + arow) * APITCH + k0 + akol) * 2);
#pragma unroll
            for (int nt = 0; nt < 4; nt++)
                LDSM_X2(bf[nt][0], bf[nt][1],
                        Bbase + ((cn + nt * 8 + brow) * APITCH + k0 + bkol) * 2);
#pragma unroll
            for (int mt = 0; mt < 4; mt++)
#pragma unroll
                for (int nt = 0; nt < 4; nt++)
                    MMA16816(acc[mt][nt], a[mt], bf[nt]);
        }

#pragma unroll
        for (int nt = 0; nt < 4; nt++) {
            int col = cn + nt * 8 + qcol;
            float bx = __ldg(b1 + col), by = __ldg(b1 + col + 1);
#pragma unroll
            for (int mt = 0; mt < 4; mt++) {
                int row = rowBase + rm + mt * 16 + qrow;
                __half2 h0 = __floats2half2_rn(gelu_exact(acc[mt][nt][0] + bx),
                                               gelu_exact(acc[mt][nt][1] + by));
                __half2 h1 = __floats2half2_rn(gelu_exact(acc[mt][nt][2] + bx),
                                               gelu_exact(acc[mt][nt][3] + by));
                *(__half2*)(hbufh_g + (size_t)row * 256 + col) = h0;
                *(__half2*)(hbufh_g + (size_t)(row + 8) * 256 + col) = h1;
            }
        }
    }
}

// ---------------------------------------------------------------
// GEMM2 (mma.sync): zt2 = ztLN + hbufh @ W2 + b2; LN2; transposed store.
// ---------------------------------------------------------------
#define G2A_OFF   0
#define G2B0_OFF  (128 * APITCH)
#define G2B1_OFF  (256 * APITCH)
#define G2RED_OFF (384 * APITCH)
#define G2_SMEM   (384 * APITCH * 2 + 4096)     // 108544 bytes
__global__ void __launch_bounds__(256) gemm2_mma(const float* __restrict__ b2,
                                                 const float* __restrict__ ln2w,
                                                 const float* __restrict__ ln2b,
                                                 float* __restrict__ out) {
    extern __shared__ __half sm2[];
    __half* Ah  = sm2 + G2A_OFF;
    __half* Bh0 = sm2 + G2B0_OFF;
    __half* Bh1 = sm2 + G2B1_OFF;
    float* redS = (float*)(sm2 + G2RED_OFF);
    float* redQ = redS + 512;
    float* stg  = (float*)sm2;
    uint32_t Abase = smem_u32(Ah);
    uint32_t Bbase0 = smem_u32(Bh0), Bbase1 = smem_u32(Bh1);

    int tid = threadIdx.x;
    int warp = tid >> 5, lane = tid & 31;
    int rowBase = blockIdx.x * 128;

    for (int idx = tid; idx < 2048; idx += 256) {
        int r = idx >> 4, kg = (idx & 15) << 3;
        *(float4*)(Ah + r * APITCH + kg) =
            *(const float4*)(hbufh_g + (size_t)(rowBase + r) * 256 + kg);
        *(float4*)(Bh0 + r * APITCH + kg) =
            *(const float4*)(W2h_g + (size_t)r * 256 + kg);
        *(float4*)(Bh1 + r * APITCH + kg) =
            *(const float4*)(W2h_g + (size_t)r * 256 + 128 + kg);
    }
    float4 pref[8];
#pragma unroll
    for (int t = 0; t < 8; t++) {
        int idx = tid + t * 256;
        int r = idx >> 4, kg = (idx & 15) << 3;
        pref[t] = *(const float4*)(hbufh_g + (size_t)(rowBase + r) * 256 + 128 + kg);
    }
    __syncthreads();

    int warp_m = warp & 1, warp_n = warp >> 1;
    int rm = warp_m * 64, cn = warp_n * 32;
    int arow = (lane & 7) + ((lane >> 3) & 1) * 8;
    int akol = (lane >> 4) * 8;
    int brow = lane & 7;
    int bkol = ((lane >> 3) & 1) * 8;

    float acc[4][4][4] = {};
#pragma unroll
    for (int kc = 0; kc < 2; kc++) {
        uint32_t Bb_ = kc ? Bbase1 : Bbase0;
#pragma unroll
        for (int ks = 0; ks < 8; ks++) {
            int k0 = ks * 16;
            uint32_t a[4][4], bf[4][2];
#pragma unroll
            for (int mt = 0; mt < 4; mt++)
                LDSM_X4(a[mt][0], a[mt][1], a[mt][2], a[mt][3],
                        Abase + ((rm + mt * 16 + arow) * APITCH + k0 + akol) * 2);
#pragma unroll
            for (int nt = 0; nt < 4; nt++)
                LDSM_X2(bf[nt][0], bf[nt][1],
                        Bb_ + ((cn + nt * 8 + brow) * APITCH + k0 + bkol) * 2);
#pragma unroll
            for (int mt = 0; mt < 4; mt++)
#pragma unroll
                for (int nt = 0; nt < 4; nt++)
                    MMA16816(acc[mt][nt], a[mt], bf[nt]);
        }
        if (kc == 0) {
            __syncthreads();
#pragma unroll
            for (int t = 0; t < 8; t++) {
                int idx = tid + t * 256;
                int r = idx >> 4, kg = (idx & 15) << 3;
                *(float4*)(Ah + r * APITCH + kg) = pref[t];
            }
            __syncthreads();
        }
    }

    int qrow = lane >> 2, qcol = (lane & 3) * 2;

#pragma unroll
    for (int mt = 0; mt < 4; mt++) {
        int rlo = rm + mt * 16 + qrow;
        int rhi = rlo + 8;
        float sLo = 0.0f, qLo = 0.0f, sHi = 0.0f, qHi = 0.0f;
#pragma unroll
        for (int nt = 0; nt < 4; nt++) {
            int col = cn + nt * 8 + qcol;
            float bx = __ldg(b2 + col), by = __ldg(b2 + col + 1);
            float2 zlo = *(const float2*)(ztLN_g + (size_t)(rowBase + rlo) * 128 + col);
            float2 zhi = *(const float2*)(ztLN_g + (size_t)(rowBase + rhi) * 128 + col);
            acc[mt][nt][0] += zlo.x + bx;
            acc[mt][nt][1] += zlo.y + by;
            acc[mt][nt][2] += zhi.x + bx;
            acc[mt][nt][3] += zhi.y + by;
            sLo += acc[mt][nt][0] + acc[mt][nt][1];
            qLo += acc[mt][nt][0] * acc[mt][nt][0] + acc[mt][nt][1] * acc[mt][nt][1];
            sHi += acc[mt][nt][2] + acc[mt][nt][3];
            qHi += acc[mt][nt][2] * acc[mt][nt][2] + acc[mt][nt][3] * acc[mt][nt][3];
        }
#pragma unroll
        for (int sh = 1; sh < 4; sh <<= 1) {
            sLo += __shfl_xor_sync(0xffffffffu, sLo, sh);
            qLo += __shfl_xor_sync(0xffffffffu, qLo, sh);
            sHi += __shfl_xor_sync(0xffffffffu, sHi, sh);
            qHi += __shfl_xor_sync(0xffffffffu, qHi, sh);
        }
        if ((lane & 3) == 0) {
            redS[rlo * 4 + warp_n] = sLo;
            redQ[rlo * 4 + warp_n] = qLo;
            redS[rhi * 4 + warp_n] = sHi;
            redQ[rhi * 4 + warp_n] = qHi;
        }
    }
    __syncthreads();

#pragma unroll
    for (int mt = 0; mt < 4; mt++) {
        int rlo = rm + mt * 16 + qrow;
        int rhi = rlo + 8;
        float sLo = redS[rlo * 4 + 0] + redS[rlo * 4 + 1] + redS[rlo * 4 + 2] + redS[rlo * 4 + 3];
        float qLo = redQ[rlo * 4 + 0] + redQ[rlo * 4 + 1] + redQ[rlo * 4 + 2] + redQ[rlo * 4 + 3];
        float sHi = redS[rhi * 4 + 0] + redS[rhi * 4 + 1] + redS[rhi * 4 + 2] + redS[rhi * 4 + 3];
        float qHi = redQ[rhi * 4 + 0] + redQ[rhi * 4 + 1] + redQ[rhi * 4 + 2] + redQ[rhi * 4 + 3];
        float mLo = sLo * (1.0f / 128.0f);
        float rLo = rsqrtf(qLo * (1.0f / 128.0f) - mLo * mLo + 1e-5f);
        float mHi = sHi * (1.0f / 128.0f);
        float rHi = rsqrtf(qHi * (1.0f / 128.0f) - mHi * mHi + 1e-5f);
#pragma unroll
        for (int nt = 0; nt < 4; nt++) {
            int col = cn + nt * 8 + qcol;
            float lwx = __ldg(ln2w + col), lwy = __ldg(ln2w + col + 1);
            float lbx = __ldg(ln2b + col), lby = __ldg(ln2b + col + 1);
            stg[(col + 0) * 132 + rlo] = (acc[mt][nt][0] - mLo) * rLo * lwx + lbx;
            stg[(col + 1) * 132 + rlo] = (acc[mt][nt][1] - mLo) * rLo * lwy + lby;
            stg[(col + 0) * 132 + rhi] = (acc[mt][nt][2] - mHi) * rHi * lwx + lbx;
            stg[(col + 1) * 132 + rhi] = (acc[mt][nt][3] - mHi) * rHi * lwy + lby;
        }
    }
    __syncthreads();

    int b = rowBase >> 14;
    int prowBase = rowBase & (Pp - 1);
    for (int idx = tid; idx < 4096; idx += 256) {
        int c = idx >> 5;
        int j = (idx & 31) * 4;
        float4 v = *(const float4*)(stg + c * 132 + j);
        *(float4*)(out + ((size_t)(b * 128 + c)) * Pp + prowBase + j) = v;
    }
}

// ---------------------------------------------------------------
extern "C" void kernel_launch(void* const* d_in, const int* in_sizes, int n_in,
                              void* d_out, int out_size) {
    const float* query = (const float*)d_in[0];
    const float* ref   = (const float*)d_in[1];
    const float* homo  = (const float*)d_in[2];
    const float* ln1w  = (const float*)d_in[3];
    const float* ln1b  = (const float*)d_in[4];
    const float* ln2w  = (const float*)d_in[5];
    const float* ln2b  = (const float*)d_in[6];
    const float* w1    = (const float*)d_in[7];
    const float* b1    = (const float*)d_in[8];
    const float* w2    = (const float*)d_in[9];
    const float* b2    = (const float*)d_in[10];
    float* out = (float*)d_out;

    cudaFuncSetAttribute(gemm1_mma, cudaFuncAttributeMaxDynamicSharedMemorySize, G1_SMEM);
    cudaFuncSetAttribute(gemm2_mma, cudaFuncAttributeMaxDynamicSharedMemorySize, G2_SMEM);

    transpose_ref_h_kernel<<<dim3(Pp / 32, 1, Bb * Nn), 256>>>(ref);
    transpose_q_kernel<<<dim3(Pp / 32, Dd / 32, Bb), dim3(32, 8)>>>(query);
    prep_w_kernel<<<256, 256>>>(w1, w2);
    attn_kernel<<<Mm / 16, 256>>>(homo, ln1w, ln1b);
    gemm1_mma<<<Mm / 128, 256, G1_SMEM>>>(b1);
    gemm2_mma<<<Mm / 128, 256, G2_SMEM>>>(b2, ln2w, ln2b, out);
}

// round 9
// speedup vs baseline: 2.6784x; 1.1186x over previous
#include <cuda_runtime.h>
#include <cuda_fp16.h>
#include <math.h>
#include <stdint.h>

#define Pp 16384
#define Dd 128
#define Bb 4
#define Nn 6
#define Mm 65536   // B*P rows

// ---- scratch (static device globals; no allocation allowed) ----
__device__ __half  refTh_g[(size_t)Bb * Nn * Pp * Dd]; // (bn, p, d) fp16
__device__ float   qT_g[(size_t)Bb * Pp * Dd];         // (bp, d) fp32
__device__ float   ztLN_g[(size_t)Bb * Pp * Dd];       // (bp, d) fp32 (residual)
__device__ __half  ztLNh_g[(size_t)Mm * Dd];           // fp16 copy for GEMM1
__device__ __half  hbufh_g[(size_t)Mm * 256];          // gelu output fp16
__device__ __half  W1h_g[256 * 128];                   // [n][k] fp16
__device__ __half  W2h_g[128 * 256];                   // [n][k] fp16

// ---------------------------------------------------------------
// helpers
// ---------------------------------------------------------------
__device__ __forceinline__ float wsum16(float v) {
#pragma unroll
    for (int s = 1; s < 16; s <<= 1) v += __shfl_xor_sync(0xffffffffu, v, s);
    return v;
}
__device__ __forceinline__ float gelu_exact(float x) {
    return 0.5f * x * (1.0f + erff(x * 0.70710678118654752440f));
}
__device__ __forceinline__ void h8_to_f8(uint4 u, float* f) {
    float2 t;
    t = __half22float2(*reinterpret_cast<__half2*>(&u.x)); f[0] = t.x; f[1] = t.y;
    t = __half22float2(*reinterpret_cast<__half2*>(&u.y)); f[2] = t.x; f[3] = t.y;
    t = __half22float2(*reinterpret_cast<__half2*>(&u.z)); f[4] = t.x; f[5] = t.y;
    t = __half22float2(*reinterpret_cast<__half2*>(&u.w)); f[6] = t.x; f[7] = t.y;
}
__device__ __forceinline__ uint32_t smem_u32(const void* p) {
    uint32_t a;
    asm("{ .reg .u64 t; cvta.to.shared.u64 t, %1; cvt.u32.u64 %0, t; }" : "=r"(a) : "l"(p));
    return a;
}

#define LDSM_X4(r0, r1, r2, r3, a) \
    asm volatile("ldmatrix.sync.aligned.m8n8.x4.shared.b16 {%0,%1,%2,%3}, [%4];" \
                 : "=r"(r0), "=r"(r1), "=r"(r2), "=r"(r3) : "r"(a))
#define LDSM_X2(r0, r1, a) \
    asm volatile("ldmatrix.sync.aligned.m8n8.x2.shared.b16 {%0,%1}, [%2];" \
                 : "=r"(r0), "=r"(r1) : "r"(a))
#define MMA16816(d, a, b) \
    asm volatile("mma.sync.aligned.m16n8k16.row.col.f32.f16.f16.f32 " \
                 "{%0,%1,%2,%3}, {%4,%5,%6,%7}, {%8,%9}, {%0,%1,%2,%3};" \
                 : "+f"((d)[0]), "+f"((d)[1]), "+f"((d)[2]), "+f"((d)[3]) \
                 : "r"((a)[0]), "r"((a)[1]), "r"((a)[2]), "r"((a)[3]), \
                   "r"((b)[0]), "r"((b)[1]))

#define APITCH 136   // halves per smem row (128 + 8 pad -> conflict-free ldmatrix)

// ---------------------------------------------------------------
// Merged prep: z<24 -> ref transpose to fp16; z in [24,28) -> q transpose
// to fp32; z==28 -> weight conversion. One launch instead of three.
// ---------------------------------------------------------------
__global__ void __launch_bounds__(256) prep_all_kernel(const float* __restrict__ ref,
                                                       const float* __restrict__ query,
                                                       const float* __restrict__ W1,
                                                       const float* __restrict__ W2) {
    int z = blockIdx.z;
    if (z == 28) {
        int idx = blockIdx.x * 256 + threadIdx.x;   // 0..131071
        if (idx < 32768) {
            int n = idx >> 7, k = idx & 127;
            W1h_g[idx] = __float2half(W1[(size_t)k * 256 + n]);
        } else if (idx < 65536) {
            int j = idx - 32768;
            int n = j >> 8, k = j & 255;
            W2h_g[j] = __float2half(W2[(size_t)k * 128 + n]);
        }
        return;
    }

    __shared__ float tile[32][129];
    int p0 = blockIdx.x * 32;
    int lane = threadIdx.x & 31;
    int ty = threadIdx.x >> 5;

    if (z < 24) {
        const float* src = ref + (size_t)z * Dd * Pp;
        __half* dst = refTh_g + (size_t)z * Pp * Dd;
#pragma unroll
        for (int it = 0; it < 16; it++) {
            int d = it * 8 + ty;
            tile[lane][d] = src[(size_t)d * Pp + p0 + lane];
        }
        __syncthreads();
        int pi = threadIdx.x & 63;
        int ppb = threadIdx.x >> 6;
#pragma unroll
        for (int it = 0; it < 8; it++) {
            int pp = it * 4 + ppb;
            float2 f = make_float2(tile[pp][2 * pi], tile[pp][2 * pi + 1]);
            *(__half2*)(dst + (size_t)(p0 + pp) * Dd + 2 * pi) = __float22half2_rn(f);
        }
    } else {
        int mat = z - 24;
        const float* src = query + (size_t)mat * Dd * Pp;
        float* dst = qT_g + (size_t)mat * Dd * Pp;
#pragma unroll
        for (int it = 0; it < 16; it++) {
            int d = it * 8 + ty;
            tile[lane][d] = src[(size_t)d * Pp + p0 + lane];
        }
        __syncthreads();
#pragma unroll
        for (int it = 0; it < 16; it++) {
            int idx = it * 256 + threadIdx.x;
            int pp = idx >> 7, d = idx & 127;
            dst[(size_t)(p0 + pp) * Dd + d] = tile[pp][d];
        }
    }
}

// ---------------------------------------------------------------
// Attention: 2 pixels/warp, 16 lanes/pixel, 8 ch/lane. Values kept as
// half2 (24 regs vs 48) + zt reuses q regs -> 4 CTAs/SM.
// ---------------------------------------------------------------
__global__ void __launch_bounds__(256, 4) attn_kernel(const float* __restrict__ homo,
                                                      const float* __restrict__ ln1w,
                                                      const float* __restrict__ ln1b) {
    int lane = threadIdx.x & 31;
    int warp = threadIdx.x >> 5;
    int sub = lane >> 4;
    int sl = lane & 15;
    int gp = blockIdx.x * 16 + warp * 2 + sub;
    int b = gp >> 14;
    int p = gp & (Pp - 1);

    float us[6], vs[6];
#pragma unroll
    for (int n = 0; n < 6; n++) {
        int bn = b * Nn + n;
        us[n] = homo[(size_t)(bn * 2 + 0) * Pp + p] * 128.0f;
        vs[n] = homo[(size_t)(bn * 2 + 1) * Pp + p] * 128.0f;
    }

    float q[8];
    {
        float4 q0 = *(const float4*)(qT_g + (size_t)gp * Dd + sl * 8);
        float4 q1 = *(const float4*)(qT_g + (size_t)gp * Dd + sl * 8 + 4);
        q[0] = q0.x; q[1] = q0.y; q[2] = q0.z; q[3] = q0.w;
        q[4] = q1.x; q[5] = q1.y; q[6] = q1.z; q[7] = q1.w;
    }
    float qn2 = 0.0f;
#pragma unroll
    for (int k = 0; k < 8; k++) qn2 += q[k] * q[k];
    qn2 = wsum16(qn2);
    float qden = fmaxf(sqrtf(qn2), 1e-12f);

    __half2 vh[6][4];
    float dots[6];

#pragma unroll
    for (int n = 0; n < 6; n++) {
        int bn = b * Nn + n;
        float u = us[n], v = vs[n];
        float wx = u - floorf(u), wy = v - floorf(v);
        int ix0 = min(max(__float2int_rd(u), 0), 127);
        int ix1 = min(max(__float2int_rd(u) + 1, 0), 127);
        int iy0 = min(max(__float2int_rd(v), 0), 127);
        int iy1 = min(max(__float2int_rd(v) + 1, 0), 127);
        bool valid = (u >= 0.0f) && (u <= 127.0f) && (v >= 0.0f) && (v <= 127.0f);

        const __half* base = refTh_g + (size_t)bn * Pp * Dd + sl * 8;
        uint4 r00 = *(const uint4*)(base + ((iy0 << 7) + ix0) * Dd);
        uint4 r10 = *(const uint4*)(base + ((iy0 << 7) + ix1) * Dd);
        uint4 r01 = *(const uint4*)(base + ((iy1 << 7) + ix0) * Dd);
        uint4 r11 = *(const uint4*)(base + ((iy1 << 7) + ix1) * Dd);

        float c00[8], c10[8], c01[8], c11[8];
        h8_to_f8(r00, c00); h8_to_f8(r10, c10);
        h8_to_f8(r01, c01); h8_to_f8(r11, c11);

        float w00 = (1.0f - wx) * (1.0f - wy);
        float w10 = wx * (1.0f - wy);
        float w01 = (1.0f - wx) * wy;
        float w11 = wx * wy;

        float v2 = 0.0f, s = 0.0f;
#pragma unroll
        for (int k = 0; k < 8; k += 2) {
            float val0 = w00 * c00[k] + w10 * c10[k] + w01 * c01[k] + w11 * c11[k];
            float val1 = w00 * c00[k + 1] + w10 * c10[k + 1] + w01 * c01[k + 1] + w11 * c11[k + 1];
            vh[n][k >> 1] = __floats2half2_rn(val0, val1);
            v2 += val0 * val0 + val1 * val1;
            s += q[k] * val0 + q[k + 1] * val1;
        }
        v2 = wsum16(v2);
        s = wsum16(s);
        float vden = fmaxf(sqrtf(v2), 1e-12f);
        dots[n] = valid ? __fdividef(s, qden * vden) : 0.0f;
    }

    float m = dots[0];
#pragma unroll
    for (int n = 1; n < 6; n++) m = fmaxf(m, dots[n]);
    float e[6], esum = 0.0f;
#pragma unroll
    for (int n = 0; n < 6; n++) { e[n] = __expf(dots[n] - m); esum += e[n]; }
    float inv = __fdividef(1.0f, esum);

    // zt accumulated into q
#pragma unroll
    for (int k2 = 0; k2 < 4; k2++) {
        float zx = 0.0f, zy = 0.0f;
#pragma unroll
        for (int n = 0; n < 6; n++) {
            float2 vv = __half22float2(vh[n][k2]);
            zx += e[n] * vv.x;
            zy += e[n] * vv.y;
        }
        q[2 * k2] += zx * inv;
        q[2 * k2 + 1] += zy * inv;
    }

    float ssum = 0.0f;
#pragma unroll
    for (int k = 0; k < 8; k++) ssum += q[k];
    float mean = wsum16(ssum) * (1.0f / 128.0f);
    float dv = 0.0f;
#pragma unroll
    for (int k = 0; k < 8; k++) { float dd = q[k] - mean; dv += dd * dd; }
    float rstd = rsqrtf(wsum16(dv) * (1.0f / 128.0f) + 1e-5f);

    float o[8];
    {
        float4 lw0 = *(const float4*)(ln1w + sl * 8);
        float4 lw1 = *(const float4*)(ln1w + sl * 8 + 4);
        float4 lb0 = *(const float4*)(ln1b + sl * 8);
        float4 lb1 = *(const float4*)(ln1b + sl * 8 + 4);
        o[0] = (q[0] - mean) * rstd * lw0.x + lb0.x;
        o[1] = (q[1] - mean) * rstd * lw0.y + lb0.y;
        o[2] = (q[2] - mean) * rstd * lw0.z + lb0.z;
        o[3] = (q[3] - mean) * rstd * lw0.w + lb0.w;
        o[4] = (q[4] - mean) * rstd * lw1.x + lb1.x;
        o[5] = (q[5] - mean) * rstd * lw1.y + lb1.y;
        o[6] = (q[6] - mean) * rstd * lw1.z + lb1.z;
        o[7] = (q[7] - mean) * rstd * lw1.w + lb1.w;
    }
    float* dstf = ztLN_g + (size_t)gp * Dd + sl * 8;
    *(float4*)dstf = make_float4(o[0], o[1], o[2], o[3]);
    *(float4*)(dstf + 4) = make_float4(o[4], o[5], o[6], o[7]);

    __half2 h[4];
    h[0] = __floats2half2_rn(o[0], o[1]);
    h[1] = __floats2half2_rn(o[2], o[3]);
    h[2] = __floats2half2_rn(o[4], o[5]);
    h[3] = __floats2half2_rn(o[6], o[7]);
    *(float4*)(ztLNh_g + (size_t)gp * Dd + sl * 8) = *(float4*)h;
}

// ---------------------------------------------------------------
// GEMM1 (mma.sync): H = gelu(ztLNh @ W1 + b1). A loaded once per CTA,
// full N=256 in smem, two column-halves computed serially from same A.
// ---------------------------------------------------------------
#define G1_SMEM (128 * APITCH * 2 + 256 * APITCH * 2)   // 104448
__global__ void __launch_bounds__(256) gemm1_mma(const float* __restrict__ b1) {
    extern __shared__ __half sm1[];
    __half* Ah = sm1;
    __half* Bh = sm1 + 128 * APITCH;
    uint32_t Abase = smem_u32(Ah), Bbase = smem_u32(Bh);

    int tid = threadIdx.x;
    int warp = tid >> 5, lane = tid & 31;
    int rowBase = blockIdx.x * 128;

    for (int idx = tid; idx < 2048; idx += 256) {
        int r = idx >> 4, kg = (idx & 15) << 3;
        *(float4*)(Ah + r * APITCH + kg) =
            *(const float4*)(ztLNh_g + (size_t)(rowBase + r) * 128 + kg);
    }
    for (int idx = tid; idx < 4096; idx += 256) {
        int r = idx >> 4, kg = (idx & 15) << 3;
        *(float4*)(Bh + r * APITCH + kg) =
            *(const float4*)(W1h_g + (size_t)r * 128 + kg);
    }
    __syncthreads();

    int warp_m = warp & 1, warp_n = warp >> 1;
    int rm = warp_m * 64;
    int arow = (lane & 7) + ((lane >> 3) & 1) * 8;
    int akol = (lane >> 4) * 8;
    int brow = lane & 7;
    int bkol = ((lane >> 3) & 1) * 8;
    int qrow = lane >> 2, qcol = (lane & 3) * 2;

#pragma unroll
    for (int nh = 0; nh < 2; nh++) {
        int cn = nh * 128 + warp_n * 32;
        float acc[4][4][4] = {};
#pragma unroll
        for (int ks = 0; ks < 8; ks++) {
            int k0 = ks * 16;
            uint32_t a[4][4], bf[4][2];
#pragma unroll
            for (int mt = 0; mt < 4; mt++)
                LDSM_X4(a[mt][0], a[mt][1], a[mt][2], a[mt][3],
                        Abase + ((rm + mt * 16 + arow) * APITCH + k0 + akol) * 2);
#pragma unroll
            for (int nt = 0; nt < 4; nt++)
                LDSM_X2(bf[nt][0], bf[nt][1],
                        Bbase + ((cn + nt * 8 + brow) * APITCH + k0 + bkol) * 2);
#pragma unroll
            for (int mt = 0; mt < 4; mt++)
#pragma unroll
                for (int nt = 0; nt < 4; nt++)
                    MMA16816(acc[mt][nt], a[mt], bf[nt]);
        }

#pragma unroll
        for (int nt = 0; nt < 4; nt++) {
            int col = cn + nt * 8 + qcol;
            float bx = __ldg(b1 + col), by = __ldg(b1 + col + 1);
#pragma unroll
            for (int mt = 0; mt < 4; mt++) {
                int row = rowBase + rm + mt * 16 + qrow;
                __half2 h0 = __floats2half2_rn(gelu_exact(acc[mt][nt][0] + bx),
                                               gelu_exact(acc[mt][nt][1] + by));
                __half2 h1 = __floats2half2_rn(gelu_exact(acc[mt][nt][2] + bx),
                                               gelu_exact(acc[mt][nt][3] + by));
                *(__half2*)(hbufh_g + (size_t)row * 256 + col) = h0;
                *(__half2*)(hbufh_g + (size_t)(row + 8) * 256 + col) = h1;
            }
        }
    }
}

// ---------------------------------------------------------------
// GEMM2 (mma.sync): zt2 = ztLN + hbufh @ W2 + b2; LN2; transposed store.
// ---------------------------------------------------------------
#define G2A_OFF   0
#define G2B0_OFF  (128 * APITCH)
#define G2B1_OFF  (256 * APITCH)
#define G2RED_OFF (384 * APITCH)
#define G2_SMEM   (384 * APITCH * 2 + 4096)     // 108544 bytes
__global__ void __launch_bounds__(256) gemm2_mma(const float* __restrict__ b2,
                                                 const float* __restrict__ ln2w,
                                                 const float* __restrict__ ln2b,
                                                 float* __restrict__ out) {
    extern __shared__ __half sm2[];
    __half* Ah  = sm2 + G2A_OFF;
    __half* Bh0 = sm2 + G2B0_OFF;
    __half* Bh1 = sm2 + G2B1_OFF;
    float* redS = (float*)(sm2 + G2RED_OFF);
    float* redQ = redS + 512;
    float* stg  = (float*)sm2;
    uint32_t Abase = smem_u32(Ah);
    uint32_t Bbase0 = smem_u32(Bh0), Bbase1 = smem_u32(Bh1);

    int tid = threadIdx.x;
    int warp = tid >> 5, lane = tid & 31;
    int rowBase = blockIdx.x * 128;

    for (int idx = tid; idx < 2048; idx += 256) {
        int r = idx >> 4, kg = (idx & 15) << 3;
        *(float4*)(Ah + r * APITCH + kg) =
            *(const float4*)(hbufh_g + (size_t)(rowBase + r) * 256 + kg);
        *(float4*)(Bh0 + r * APITCH + kg) =
            *(const float4*)(W2h_g + (size_t)r * 256 + kg);
        *(float4*)(Bh1 + r * APITCH + kg) =
            *(const float4*)(W2h_g + (size_t)r * 256 + 128 + kg);
    }
    float4 pref[8];
#pragma unroll
    for (int t = 0; t < 8; t++) {
        int idx = tid + t * 256;
        int r = idx >> 4, kg = (idx & 15) << 3;
        pref[t] = *(const float4*)(hbufh_g + (size_t)(rowBase + r) * 256 + 128 + kg);
    }
    __syncthreads();

    int warp_m = warp & 1, warp_n = warp >> 1;
    int rm = warp_m * 64, cn = warp_n * 32;
    int arow = (lane & 7) + ((lane >> 3) & 1) * 8;
    int akol = (lane >> 4) * 8;
    int brow = lane & 7;
    int bkol = ((lane >> 3) & 1) * 8;

    float acc[4][4][4] = {};
#pragma unroll
    for (int kc = 0; kc < 2; kc++) {
        uint32_t Bb_ = kc ? Bbase1 : Bbase0;
#pragma unroll
        for (int ks = 0; ks < 8; ks++) {
            int k0 = ks * 16;
            uint32_t a[4][4], bf[4][2];
#pragma unroll
            for (int mt = 0; mt < 4; mt++)
                LDSM_X4(a[mt][0], a[mt][1], a[mt][2], a[mt][3],
                        Abase + ((rm + mt * 16 + arow) * APITCH + k0 + akol) * 2);
#pragma unroll
            for (int nt = 0; nt < 4; nt++)
                LDSM_X2(bf[nt][0], bf[nt][1],
                        Bb_ + ((cn + nt * 8 + brow) * APITCH + k0 + bkol) * 2);
#pragma unroll
            for (int mt = 0; mt < 4; mt++)
#pragma unroll
                for (int nt = 0; nt < 4; nt++)
                    MMA16816(acc[mt][nt], a[mt], bf[nt]);
        }
        if (kc == 0) {
            __syncthreads();
#pragma unroll
            for (int t = 0; t < 8; t++) {
                int idx = tid + t * 256;
                int r = idx >> 4, kg = (idx & 15) << 3;
                *(float4*)(Ah + r * APITCH + kg) = pref[t];
            }
            __syncthreads();
        }
    }

    int qrow = lane >> 2, qcol = (lane & 3) * 2;

#pragma unroll
    for (int mt = 0; mt < 4; mt++) {
        int rlo = rm + mt * 16 + qrow;
        int rhi = rlo + 8;
        float sLo = 0.0f, qLo = 0.0f, sHi = 0.0f, qHi = 0.0f;
#pragma unroll
        for (int nt = 0; nt < 4; nt++) {
            int col = cn + nt * 8 + qcol;
            float bx = __ldg(b2 + col), by = __ldg(b2 + col + 1);
            float2 zlo = *(const float2*)(ztLN_g + (size_t)(rowBase + rlo) * 128 + col);
            float2 zhi = *(const float2*)(ztLN_g + (size_t)(rowBase + rhi) * 128 + col);
            acc[mt][nt][0] += zlo.x + bx;
            acc[mt][nt][1] += zlo.y + by;
            acc[mt][nt][2] += zhi.x + bx;
            acc[mt][nt][3] += zhi.y + by;
            sLo += acc[mt][nt][0] + acc[mt][nt][1];
            qLo += acc[mt][nt][0] * acc[mt][nt][0] + acc[mt][nt][1] * acc[mt][nt][1];
            sHi += acc[mt][nt][2] + acc[mt][nt][3];
            qHi += acc[mt][nt][2] * acc[mt][nt][2] + acc[mt][nt][3] * acc[mt][nt][3];
        }
#pragma unroll
        for (int sh = 1; sh < 4; sh <<= 1) {
            sLo += __shfl_xor_sync(0xffffffffu, sLo, sh);
            qLo += __shfl_xor_sync(0xffffffffu, qLo, sh);
            sHi += __shfl_xor_sync(0xffffffffu, sHi, sh);
            qHi += __shfl_xor_sync(0xffffffffu, qHi, sh);
        }
        if ((lane & 3) == 0) {
            redS[rlo * 4 + warp_n] = sLo;
            redQ[rlo * 4 + warp_n] = qLo;
            redS[rhi * 4 + warp_n] = sHi;
            redQ[rhi * 4 + warp_n] = qHi;
        }
    }
    __syncthreads();

#pragma unroll
    for (int mt = 0; mt < 4; mt++) {
        int rlo = rm + mt * 16 + qrow;
        int rhi = rlo + 8;
        float sLo = redS[rlo * 4 + 0] + redS[rlo * 4 + 1] + redS[rlo * 4 + 2] + redS[rlo * 4 + 3];
        float qLo = redQ[rlo * 4 + 0] + redQ[rlo * 4 + 1] + redQ[rlo * 4 + 2] + redQ[rlo * 4 + 3];
        float sHi = redS[rhi * 4 + 0] + redS[rhi * 4 + 1] + redS[rhi * 4 + 2] + redS[rhi * 4 + 3];
        float qHi = redQ[rhi * 4 + 0] + redQ[rhi * 4 + 1] + redQ[rhi * 4 + 2] + redQ[rhi * 4 + 3];
        float mLo = sLo * (1.0f / 128.0f);
        float rLo = rsqrtf(qLo * (1.0f / 128.0f) - mLo * mLo + 1e-5f);
        float mHi = sHi * (1.0f / 128.0f);
        float rHi = rsqrtf(qHi * (1.0f / 128.0f) - mHi * mHi + 1e-5f);
#pragma unroll
        for (int nt = 0; nt < 4; nt++) {
            int col = cn + nt * 8 + qcol;
            float lwx = __ldg(ln2w + col), lwy = __ldg(ln2w + col + 1);
            float lbx = __ldg(ln2b + col), lby = __ldg(ln2b + col + 1);
            stg[(col + 0) * 132 + rlo] = (acc[mt][nt][0] - mLo) * rLo * lwx + lbx;
            stg[(col + 1) * 132 + rlo] = (acc[mt][nt][1] - mLo) * rLo * lwy + lby;
            stg[(col + 0) * 132 + rhi] = (acc[mt][nt][2] - mHi) * rHi * lwx + lbx;
            stg[(col + 1) * 132 + rhi] = (acc[mt][nt][3] - mHi) * rHi * lwy + lby;
        }
    }
    __syncthreads();

    int b = rowBase >> 14;
    int prowBase = rowBase & (Pp - 1);
    for (int idx = tid; idx < 4096; idx += 256) {
        int c = idx >> 5;
        int j = (idx & 31) * 4;
        float4 v = *(const float4*)(stg + c * 132 + j);
        *(float4*)(out + ((size_t)(b * 128 + c)) * Pp + prowBase + j) = v;
    }
}

// ---------------------------------------------------------------
extern "C" void kernel_launch(void* const* d_in, const int* in_sizes, int n_in,
                              void* d_out, int out_size) {
    const float* query = (const float*)d_in[0];
    const float* ref   = (const float*)d_in[1];
    const float* homo  = (const float*)d_in[2];
    const float* ln1w  = (const float*)d_in[3];
    const float* ln1b  = (const float*)d_in[4];
    const float* ln2w  = (const float*)d_in[5];
    const float* ln2b  = (const float*)d_in[6];
    const float* w1    = (const float*)d_in[7];
    const float* b1    = (const float*)d_in[8];
    const float* w2    = (const float*)d_in[9];
    const float* b2    = (const float*)d_in[10];
    float* out = (float*)d_out;

    cudaFuncSetAttribute(gemm1_mma, cudaFuncAttributeMaxDynamicSharedMemorySize, G1_SMEM);
    cudaFuncSetAttribute(gemm2_mma, cudaFuncAttributeMaxDynamicSharedMemorySize, G2_SMEM);

    prep_all_kernel<<<dim3(Pp / 32, 1, 29), 256>>>(ref, query, w1, w2);
    attn_kernel<<<Mm / 16, 256>>>(homo, ln1w, ln1b);
    gemm1_mma<<<Mm / 128, 256, G1_SMEM>>>(b1);
    gemm2_mma<<<Mm / 128, 256, G2_SMEM>>>(b2, ln2w, ln2b, out);
}